// round 9
// baseline (speedup 1.0000x reference)
#include <cuda_runtime.h>
#include <math.h>
#include <stdint.h>

#define BATCH   2
#define SEQ     2048
#define DMODEL  1024
#define NHEADS  16
#define HDIM    64
#define BLK     64
#define NB      (SEQ/BLK)         // 32 key blocks per batch
#define MROWS   (BATCH*SEQ)       // 4096

#define QP      68                // qp/ks pitch (words)
#define VP      72                // vs pitch (words)
#define APIT    20                // GEMM A smem pitch
#define BPIT    136               // GEMM B smem pitch

// Scratch (device globals: allocation-free, graph-capture safe).
// g_q/g_k/g_v/g_attn hold tf32 bit patterns (uint32).
__device__ __align__(16) uint32_t g_q[MROWS*DMODEL];
__device__ __align__(16) uint32_t g_k[MROWS*DMODEL];
__device__ __align__(16) uint32_t g_v[MROWS*DMODEL];
__device__ __align__(16) uint32_t g_attn[MROWS*DMODEL];
__device__ __align__(16) uint32_t g_xt[MROWS*DMODEL];      // x in tf32 bits
__device__ __align__(16) uint32_t g_wq[DMODEL*DMODEL];
__device__ __align__(16) uint32_t g_wk[DMODEL*DMODEL];
__device__ __align__(16) uint32_t g_wv[DMODEL*DMODEL];
__device__ __align__(16) uint32_t g_wo[DMODEL*DMODEL];

// ---------------------------------------------------------------------------
// helpers
// ---------------------------------------------------------------------------
__device__ __forceinline__ uint32_t f2tf32(float f) {
    uint32_t u;
    asm("cvt.rna.tf32.f32 %0, %1;" : "=r"(u) : "f"(f));
    return u;
}

__device__ __forceinline__ void mma_tf32(float* d, const uint32_t* a, const uint32_t* b) {
    asm volatile(
        "mma.sync.aligned.m16n8k8.row.col.f32.tf32.tf32.f32 "
        "{%0,%1,%2,%3}, {%4,%5,%6,%7}, {%8,%9}, {%0,%1,%2,%3};"
        : "+f"(d[0]), "+f"(d[1]), "+f"(d[2]), "+f"(d[3])
        : "r"(a[0]), "r"(a[1]), "r"(a[2]), "r"(a[3]),
          "r"(b[0]), "r"(b[1]));
}

__device__ __forceinline__ void cp16(uint32_t smem_addr, const void* gptr) {
    asm volatile("cp.async.cg.shared.global [%0], [%1], 16;\n"
                 :: "r"(smem_addr), "l"(gptr));
}
__device__ __forceinline__ void cp_commit() {
    asm volatile("cp.async.commit_group;\n" ::: "memory");
}
__device__ __forceinline__ void cp_wait_all() {
    asm volatile("cp.async.wait_group 0;\n" ::: "memory");
}

// ---------------------------------------------------------------------------
// elementwise fp32 -> tf32-bits conversion
// ---------------------------------------------------------------------------
__global__ void conv_tf32(const float4* __restrict__ in, uint4* __restrict__ out, int n4)
{
    int i = blockIdx.x * blockDim.x + threadIdx.x;
    if (i < n4) {
        float4 v = in[i];
        out[i] = make_uint4(f2tf32(v.x), f2tf32(v.y), f2tf32(v.z), f2tf32(v.w));
    }
}

// ---------------------------------------------------------------------------
// TF32 GEMM with cp.async double buffering. Inputs A, W already tf32 bits.
// C[M,N] = A[M,K] @ W[K,N] + bias.
// OMODE 0: fp32 out; 1: tf32-bits out; 2: tf32-bits of 0.125*(acc+bias).
// 128x128 tile, 256 threads (8 warps, 64x32 each), k-tile 16.
// ---------------------------------------------------------------------------
template<int OMODE>
__global__ __launch_bounds__(256, 2)
void gemm_tf32(const uint32_t* __restrict__ A, const uint32_t* __restrict__ W,
               const float* __restrict__ bias, uint32_t* __restrict__ C,
               int M, int N, int K)
{
    __shared__ uint32_t As[2][128 * APIT];
    __shared__ uint32_t Bs[2][16 * BPIT];

    const int tid  = threadIdx.x;
    const int lane = tid & 31;
    const int wid  = tid >> 5;
    const int gi   = lane >> 2;
    const int tg   = lane & 3;
    const int m0   = (wid >> 2) * 64;
    const int n0   = (wid & 3) * 32;
    const int bm   = blockIdx.y * 128;
    const int bn   = blockIdx.x * 128;

    const int a_r = tid >> 2;              // 0..63 (and +64)
    const int a_o = (tid & 3) * 4;
    const int b_r = tid >> 5;              // 0..7 (and +8)
    const int b_o = (tid & 31) * 4;

    const uint32_t as_base = (uint32_t)__cvta_generic_to_shared(&As[0][0]);
    const uint32_t bs_base = (uint32_t)__cvta_generic_to_shared(&Bs[0][0]);

    float acc[4][4][4];
#pragma unroll
    for (int i = 0; i < 4; i++)
#pragma unroll
        for (int j = 0; j < 4; j++)
#pragma unroll
            for (int r = 0; r < 4; r++) acc[i][j][r] = 0.f;

    const int nkt = K / 16;

    // prologue: k-tile 0 -> buf 0
    {
        cp16(as_base + (uint32_t)((a_r * APIT + a_o) * 4),
             A + (size_t)(bm + a_r) * K + a_o);
        cp16(as_base + (uint32_t)(((a_r + 64) * APIT + a_o) * 4),
             A + (size_t)(bm + a_r + 64) * K + a_o);
        cp16(bs_base + (uint32_t)((b_r * BPIT + b_o) * 4),
             W + (size_t)(b_r) * N + bn + b_o);
        cp16(bs_base + (uint32_t)(((b_r + 8) * BPIT + b_o) * 4),
             W + (size_t)(b_r + 8) * N + bn + b_o);
        cp_commit();
    }

    for (int kt = 0; kt < nkt; kt++) {
        const int buf = kt & 1;
        cp_wait_all();
        __syncthreads();

        if (kt + 1 < nkt) {
            const int nb2 = buf ^ 1;
            const int ko  = (kt + 1) * 16;
            const uint32_t abuf = as_base + (uint32_t)(nb2 * 128 * APIT * 4);
            const uint32_t bbuf = bs_base + (uint32_t)(nb2 * 16 * BPIT * 4);
            cp16(abuf + (uint32_t)((a_r * APIT + a_o) * 4),
                 A + (size_t)(bm + a_r) * K + ko + a_o);
            cp16(abuf + (uint32_t)(((a_r + 64) * APIT + a_o) * 4),
                 A + (size_t)(bm + a_r + 64) * K + ko + a_o);
            cp16(bbuf + (uint32_t)((b_r * BPIT + b_o) * 4),
                 W + (size_t)(ko + b_r) * N + bn + b_o);
            cp16(bbuf + (uint32_t)(((b_r + 8) * BPIT + b_o) * 4),
                 W + (size_t)(ko + b_r + 8) * N + bn + b_o);
            cp_commit();
        }

#pragma unroll
        for (int ks = 0; ks < 2; ks++) {
            uint32_t af[4][4], bf[4][2];
#pragma unroll
            for (int mf = 0; mf < 4; mf++) {
                const uint32_t* p = &As[buf][(m0 + 16*mf + gi) * APIT + 8*ks + tg];
                af[mf][0] = p[0];
                af[mf][1] = p[8 * APIT];
                af[mf][2] = p[4];
                af[mf][3] = p[8 * APIT + 4];
            }
#pragma unroll
            for (int nf = 0; nf < 4; nf++) {
                bf[nf][0] = Bs[buf][(8*ks + tg) * BPIT + n0 + 8*nf + gi];
                bf[nf][1] = Bs[buf][(8*ks + tg + 4) * BPIT + n0 + 8*nf + gi];
            }
#pragma unroll
            for (int mf = 0; mf < 4; mf++)
#pragma unroll
                for (int nf = 0; nf < 4; nf++)
                    mma_tf32(acc[mf][nf], af[mf], bf[nf]);
        }
        __syncthreads();
    }

    // epilogue
#pragma unroll
    for (int mf = 0; mf < 4; mf++) {
        const int r0 = bm + m0 + 16*mf + gi;
        const int r1 = r0 + 8;
#pragma unroll
        for (int nf = 0; nf < 4; nf++) {
            const int c = bn + n0 + 8*nf + 2*tg;
            float2 bi = *(const float2*)&bias[c];
            float v00 = acc[mf][nf][0] + bi.x, v01 = acc[mf][nf][1] + bi.y;
            float v10 = acc[mf][nf][2] + bi.x, v11 = acc[mf][nf][3] + bi.y;
            if (OMODE == 0) {
                *(float2*)&((float*)C)[(size_t)r0 * N + c] = make_float2(v00, v01);
                *(float2*)&((float*)C)[(size_t)r1 * N + c] = make_float2(v10, v11);
            } else {
                if (OMODE == 2) { v00 *= 0.125f; v01 *= 0.125f; v10 *= 0.125f; v11 *= 0.125f; }
                *(uint2*)&C[(size_t)r0 * N + c] = make_uint2(f2tf32(v00), f2tf32(v01));
                *(uint2*)&C[(size_t)r1 * N + c] = make_uint2(f2tf32(v10), f2tf32(v11));
            }
        }
    }
}

// ---------------------------------------------------------------------------
// TF32 flash attention v4: one CTA per (qblock-PAIR, head, batch).
// 128 threads, 4 warps; warp w owns query rows 32w..32w+31.
// Each 64-key tile is processed as TWO complete flash steps of 32 keys:
// QK-half -> softmax update -> P-store -> PV-half. This keeps P in smem
// always normalized to the current running max (fixes R6 bug).
// ---------------------------------------------------------------------------
__global__ __launch_bounds__(128, 2)
void attn_tf32(const float* __restrict__ G)
{
    extern __shared__ uint32_t sm[];
    uint32_t* qp = sm;                               // Q staging then P [128][QP]
    uint32_t* ks = sm + 128 * QP;                    // 2 x [64][QP]
    uint32_t* vs = sm + 128 * QP + 2 * 64 * QP;      // 2 x [64][VP]
    __shared__ float kbuf[128];

    const int p = blockIdx.x, h = blockIdx.y, b = blockIdx.z;
    const int row0 = p * 128;
    const int tid  = threadIdx.x;
    const int lane = tid & 31;
    const int w    = tid >> 5;
    const int gi   = lane >> 2;
    const int tg   = lane & 3;

    // ---- keep masks for the two query blocks of this pair ----
    kbuf[tid] = fabsf(G[b * SEQ + row0 + tid]);
    __syncthreads();
    float mx0 = 0.f, mx1 = 0.f;
#pragma unroll
    for (int i = 0; i < 64; i++) { mx0 = fmaxf(mx0, kbuf[i]); mx1 = fmaxf(mx1, kbuf[64 + i]); }
    const bool keep0 = (mx0 >= 0.99f);
    const bool keep1 = (mx1 >= 0.99f);

    if (!keep0 && !keep1) {
        const uint4 z = make_uint4(0u, 0u, 0u, 0u);
#pragma unroll
        for (int i = 0; i < 16; i++) {
            int c = tid + i * 128;
            int r = c >> 4;
            int o = (c & 15) * 4;
            *(uint4*)&g_attn[(size_t)(b * SEQ + row0 + r) * DMODEL + h * HDIM + o] = z;
        }
        return;
    }
    const bool wkeep = (w < 2) ? keep0 : keep1;

    const uint32_t qp_sa = (uint32_t)__cvta_generic_to_shared(qp);
    const uint32_t ks_sa = (uint32_t)__cvta_generic_to_shared(ks);
    const uint32_t vs_sa = (uint32_t)__cvta_generic_to_shared(vs);

    // ---- prologue: Q (128x64) + K/V tile 0 via cp.async ----
#pragma unroll
    for (int i = 0; i < 16; i++) {                   // Q: 2048 chunks / 128 thr
        int c = tid + i * 128;
        int r = c >> 4;
        int o = (c & 15) * 4;
        cp16(qp_sa + (uint32_t)((r * QP + o) * 4),
             g_q + (size_t)(b * SEQ + row0 + r) * DMODEL + h * HDIM + o);
    }
#pragma unroll
    for (int i = 0; i < 8; i++) {                    // K/V tile 0: 1024 chunks each
        int c = tid + i * 128;
        int r = c >> 4;
        int o = (c & 15) * 4;
        size_t src = (size_t)(b * SEQ + r) * DMODEL + h * HDIM + o;
        cp16(ks_sa + (uint32_t)((r * QP + o) * 4), g_k + src);
        cp16(vs_sa + (uint32_t)((r * VP + o) * 4), g_v + src);
    }
    cp_commit();

    uint32_t qa[2][8][4];
    float o_[2][8][4];
    float m_[2][2], l_[2][2];
#pragma unroll
    for (int mf = 0; mf < 2; mf++) {
        m_[mf][0] = m_[mf][1] = -1e30f;
        l_[mf][0] = l_[mf][1] = 0.f;
#pragma unroll
        for (int nf = 0; nf < 8; nf++)
#pragma unroll
            for (int r = 0; r < 4; r++) o_[mf][nf][r] = 0.f;
    }

    for (int kb = 0; kb < NB; kb++) {
        const int buf = kb & 1;
        cp_wait_all();
        __syncthreads();

        if (kb == 0 && wkeep) {
            // extract Q A-fragments (rows warp-private; P will overwrite later)
#pragma unroll
            for (int mf = 0; mf < 2; mf++)
#pragma unroll
                for (int k8 = 0; k8 < 8; k8++) {
                    const uint32_t* q = &qp[(32*w + 16*mf + gi) * QP + 8*k8 + tg];
                    qa[mf][k8][0] = q[0];
                    qa[mf][k8][1] = q[8 * QP];
                    qa[mf][k8][2] = q[4];
                    qa[mf][k8][3] = q[8 * QP + 4];
                }
        }

        if (kb + 1 < NB) {
            const int nb2 = buf ^ 1;
            const uint32_t kd = ks_sa + (uint32_t)(nb2 * 64 * QP * 4);
            const uint32_t vd = vs_sa + (uint32_t)(nb2 * 64 * VP * 4);
#pragma unroll
            for (int i = 0; i < 8; i++) {
                int c = tid + i * 128;
                int r = c >> 4;
                int o = (c & 15) * 4;
                size_t src = (size_t)(b * SEQ + (kb + 1) * BLK + r) * DMODEL + h * HDIM + o;
                cp16(kd + (uint32_t)((r * QP + o) * 4), g_k + src);
                cp16(vd + (uint32_t)((r * VP + o) * 4), g_v + src);
            }
            cp_commit();
        }

        if (wkeep) {
            const uint32_t* ksb = ks + buf * 64 * QP;
            const uint32_t* vsb = vs + buf * 64 * VP;

            // two COMPLETE flash steps of 32 keys each
#pragma unroll
            for (int h2 = 0; h2 < 2; h2++) {
                // --- QK for this 32-key half ---
                float sc[2][4][4];
#pragma unroll
                for (int mf = 0; mf < 2; mf++)
#pragma unroll
                    for (int j = 0; j < 4; j++)
                        sc[mf][j][0] = sc[mf][j][1] = sc[mf][j][2] = sc[mf][j][3] = 0.f;

#pragma unroll
                for (int k8 = 0; k8 < 8; k8++)
#pragma unroll
                    for (int j = 0; j < 4; j++) {
                        const int nf = 4*h2 + j;
                        uint32_t bfr[2];
                        bfr[0] = ksb[(8*nf + gi) * QP + 8*k8 + tg];
                        bfr[1] = ksb[(8*nf + gi) * QP + 8*k8 + 4 + tg];
                        mma_tf32(sc[0][j], qa[0][k8], bfr);
                        mma_tf32(sc[1][j], qa[1][k8], bfr);
                    }

                __syncwarp();   // prior PV reads of P region done before overwrite

                // --- softmax update + P store (columns 0..31, this half) ---
#pragma unroll
                for (int mf = 0; mf < 2; mf++) {
                    float r0m = -1e30f, r1m = -1e30f;
#pragma unroll
                    for (int j = 0; j < 4; j++) {
                        r0m = fmaxf(r0m, fmaxf(sc[mf][j][0], sc[mf][j][1]));
                        r1m = fmaxf(r1m, fmaxf(sc[mf][j][2], sc[mf][j][3]));
                    }
                    r0m = fmaxf(r0m, __shfl_xor_sync(0xffffffffu, r0m, 1));
                    r0m = fmaxf(r0m, __shfl_xor_sync(0xffffffffu, r0m, 2));
                    r1m = fmaxf(r1m, __shfl_xor_sync(0xffffffffu, r1m, 1));
                    r1m = fmaxf(r1m, __shfl_xor_sync(0xffffffffu, r1m, 2));
                    const float mn0 = fmaxf(m_[mf][0], r0m);
                    const float mn1 = fmaxf(m_[mf][1], r1m);
                    const float al0 = __expf(m_[mf][0] - mn0);
                    const float al1 = __expf(m_[mf][1] - mn1);
                    m_[mf][0] = mn0; m_[mf][1] = mn1;

                    float s0 = 0.f, s1 = 0.f;
                    const int pr = (32*w + 16*mf + gi) * QP;
#pragma unroll
                    for (int j = 0; j < 4; j++) {
                        float p0 = __expf(sc[mf][j][0] - mn0);
                        float p1 = __expf(sc[mf][j][1] - mn0);
                        float p2 = __expf(sc[mf][j][2] - mn1);
                        float p3 = __expf(sc[mf][j][3] - mn1);
                        s0 += p0 + p1;
                        s1 += p2 + p3;
                        const int c = 8*j + 2*tg;
                        *(uint2*)&qp[pr + c]        = make_uint2(f2tf32(p0), f2tf32(p1));
                        *(uint2*)&qp[pr + 8*QP + c] = make_uint2(f2tf32(p2), f2tf32(p3));
                    }
                    s0 += __shfl_xor_sync(0xffffffffu, s0, 1);
                    s0 += __shfl_xor_sync(0xffffffffu, s0, 2);
                    s1 += __shfl_xor_sync(0xffffffffu, s1, 1);
                    s1 += __shfl_xor_sync(0xffffffffu, s1, 2);
                    l_[mf][0] = l_[mf][0] * al0 + s0;
                    l_[mf][1] = l_[mf][1] * al1 + s1;
#pragma unroll
                    for (int nf = 0; nf < 8; nf++) {
                        o_[mf][nf][0] *= al0; o_[mf][nf][1] *= al0;
                        o_[mf][nf][2] *= al1; o_[mf][nf][3] *= al1;
                    }
                }
                __syncwarp();   // P stores visible to all lanes before PV reads

                // --- PV for this half: O += P[16x32] * V[32keys x 64d] ---
#pragma unroll
                for (int k8p = 0; k8p < 4; k8p++) {
                    uint32_t pa[2][4];
#pragma unroll
                    for (int mf = 0; mf < 2; mf++) {
                        const uint32_t* pp = &qp[(32*w + 16*mf + gi) * QP + 8*k8p + tg];
                        pa[mf][0] = pp[0];
                        pa[mf][1] = pp[8 * QP];
                        pa[mf][2] = pp[4];
                        pa[mf][3] = pp[8 * QP + 4];
                    }
                    const int vr = 32*h2 + 8*k8p + tg;
#pragma unroll
                    for (int nf = 0; nf < 8; nf++) {
                        uint32_t bfr[2];
                        bfr[0] = vsb[vr * VP + 8*nf + gi];
                        bfr[1] = vsb[(vr + 4) * VP + 8*nf + gi];
                        mma_tf32(o_[0][nf], pa[0], bfr);
                        mma_tf32(o_[1][nf], pa[1], bfr);
                    }
                }
            }
        }
    }

    // ---- epilogue: write tf32 bits of O/l (zeros for skipped warp) ----
#pragma unroll
    for (int mf = 0; mf < 2; mf++) {
        const float i0 = wkeep ? 1.0f / l_[mf][0] : 0.f;
        const float i1 = wkeep ? 1.0f / l_[mf][1] : 0.f;
        const size_t r0 = (size_t)(b * SEQ + row0 + 32*w + 16*mf + gi) * DMODEL + h * HDIM;
        const size_t r1 = r0 + (size_t)8 * DMODEL;
#pragma unroll
        for (int nf = 0; nf < 8; nf++) {
            const int c = 8*nf + 2*tg;
            if (wkeep) {
                *(uint2*)&g_attn[r0 + c] = make_uint2(f2tf32(o_[mf][nf][0] * i0),
                                                      f2tf32(o_[mf][nf][1] * i0));
                *(uint2*)&g_attn[r1 + c] = make_uint2(f2tf32(o_[mf][nf][2] * i1),
                                                      f2tf32(o_[mf][nf][3] * i1));
            } else {
                *(uint2*)&g_attn[r0 + c] = make_uint2(0u, 0u);
                *(uint2*)&g_attn[r1 + c] = make_uint2(0u, 0u);
            }
        }
    }
}

// ---------------------------------------------------------------------------
extern "C" void kernel_launch(void* const* d_in, const int* in_sizes, int n_in,
                              void* d_out, int out_size)
{
    const float* x  = (const float*)d_in[0];
    const float* G  = (const float*)d_in[1];
    const float* Wq = (const float*)d_in[2];
    const float* bq = (const float*)d_in[3];
    const float* Wk = (const float*)d_in[4];
    const float* bk = (const float*)d_in[5];
    const float* Wv = (const float*)d_in[6];
    const float* bv = (const float*)d_in[7];
    const float* Wo = (const float*)d_in[8];
    const float* bo = (const float*)d_in[9];
    float* out = (float*)d_out;

    uint32_t *qp_, *kp_, *vp_, *ap_, *xt_, *wq_, *wk_, *wv_, *wo_;
    cudaGetSymbolAddress((void**)&qp_, g_q);
    cudaGetSymbolAddress((void**)&kp_, g_k);
    cudaGetSymbolAddress((void**)&vp_, g_v);
    cudaGetSymbolAddress((void**)&ap_, g_attn);
    cudaGetSymbolAddress((void**)&xt_, g_xt);
    cudaGetSymbolAddress((void**)&wq_, g_wq);
    cudaGetSymbolAddress((void**)&wk_, g_wk);
    cudaGetSymbolAddress((void**)&wv_, g_wv);
    cudaGetSymbolAddress((void**)&wo_, g_wo);

    // pre-convert inputs to tf32 bits (one pass each)
    const int xn4 = MROWS * DMODEL / 4;
    const int wn4 = DMODEL * DMODEL / 4;
    conv_tf32<<<(xn4 + 255) / 256, 256>>>((const float4*)x,  (uint4*)xt_, xn4);
    conv_tf32<<<(wn4 + 255) / 256, 256>>>((const float4*)Wq, (uint4*)wq_, wn4);
    conv_tf32<<<(wn4 + 255) / 256, 256>>>((const float4*)Wk, (uint4*)wk_, wn4);
    conv_tf32<<<(wn4 + 255) / 256, 256>>>((const float4*)Wv, (uint4*)wv_, wn4);
    conv_tf32<<<(wn4 + 255) / 256, 256>>>((const float4*)Wo, (uint4*)wo_, wn4);

    const dim3 gproj(DMODEL / 128, MROWS / 128);
    gemm_tf32<2><<<gproj, 256>>>(xt_, wq_, bq, qp_, MROWS, DMODEL, DMODEL);  // Q * 1/8
    gemm_tf32<1><<<gproj, 256>>>(xt_, wk_, bk, kp_, MROWS, DMODEL, DMODEL);
    gemm_tf32<1><<<gproj, 256>>>(xt_, wv_, bv, vp_, MROWS, DMODEL, DMODEL);

    const int attn_smem = (128 * QP + 2 * 64 * QP + 2 * 64 * VP) * (int)sizeof(uint32_t); // 106,496 B
    cudaFuncSetAttribute(attn_tf32, cudaFuncAttributeMaxDynamicSharedMemorySize, attn_smem);
    attn_tf32<<<dim3(SEQ / 128, NHEADS, BATCH), 128, attn_smem>>>(G);

    gemm_tf32<0><<<gproj, 256>>>(ap_, wo_, bo, (uint32_t*)out, MROWS, DMODEL, DMODEL);
}

// round 11
// speedup vs baseline: 1.1065x; 1.1065x over previous
#include <cuda_runtime.h>
#include <math.h>
#include <stdint.h>

#define BATCH   2
#define SEQ     2048
#define DMODEL  1024
#define NHEADS  16
#define HDIM    64
#define BLK     64
#define NB      (SEQ/BLK)         // 32 key blocks per batch
#define MROWS   (BATCH*SEQ)       // 4096

#define QP      68                // qs/ks pitch (words)
#define VP      72                // vs pitch (words)
#define APIT    20                // GEMM A smem pitch
#define BPIT    136               // GEMM B smem pitch

// Scratch (device globals: allocation-free, graph-capture safe).
// g_q/g_k/g_v/g_attn hold tf32 bit patterns (uint32).
__device__ __align__(16) uint32_t g_q[MROWS*DMODEL];
__device__ __align__(16) uint32_t g_k[MROWS*DMODEL];
__device__ __align__(16) uint32_t g_v[MROWS*DMODEL];
__device__ __align__(16) uint32_t g_attn[MROWS*DMODEL];
__device__ __align__(16) uint32_t g_xt[MROWS*DMODEL];      // x in tf32 bits
__device__ __align__(16) uint32_t g_wq[DMODEL*DMODEL];
__device__ __align__(16) uint32_t g_wk[DMODEL*DMODEL];
__device__ __align__(16) uint32_t g_wv[DMODEL*DMODEL];
__device__ __align__(16) uint32_t g_wo[DMODEL*DMODEL];

// ---------------------------------------------------------------------------
// helpers
// ---------------------------------------------------------------------------
__device__ __forceinline__ uint32_t f2tf32(float f) {
    uint32_t u;
    asm("cvt.rna.tf32.f32 %0, %1;" : "=r"(u) : "f"(f));
    return u;
}

__device__ __forceinline__ void mma_tf32(float* d, const uint32_t* a, const uint32_t* b) {
    asm volatile(
        "mma.sync.aligned.m16n8k8.row.col.f32.tf32.tf32.f32 "
        "{%0,%1,%2,%3}, {%4,%5,%6,%7}, {%8,%9}, {%0,%1,%2,%3};"
        : "+f"(d[0]), "+f"(d[1]), "+f"(d[2]), "+f"(d[3])
        : "r"(a[0]), "r"(a[1]), "r"(a[2]), "r"(a[3]),
          "r"(b[0]), "r"(b[1]));
}

__device__ __forceinline__ void cp16(uint32_t smem_addr, const void* gptr) {
    asm volatile("cp.async.cg.shared.global [%0], [%1], 16;\n"
                 :: "r"(smem_addr), "l"(gptr));
}
__device__ __forceinline__ void cp_commit() {
    asm volatile("cp.async.commit_group;\n" ::: "memory");
}
__device__ __forceinline__ void cp_wait_all() {
    asm volatile("cp.async.wait_group 0;\n" ::: "memory");
}
__device__ __forceinline__ void cp_wait_1() {
    asm volatile("cp.async.wait_group 1;\n" ::: "memory");
}

// ---------------------------------------------------------------------------
// elementwise fp32 -> tf32-bits conversion
// ---------------------------------------------------------------------------
__global__ void conv_tf32(const float4* __restrict__ in, uint4* __restrict__ out, int n4)
{
    int i = blockIdx.x * blockDim.x + threadIdx.x;
    if (i < n4) {
        float4 v = in[i];
        out[i] = make_uint4(f2tf32(v.x), f2tf32(v.y), f2tf32(v.z), f2tf32(v.w));
    }
}

// ---------------------------------------------------------------------------
// TF32 GEMM, 3-stage cp.async pipeline. Inputs A, W already tf32 bits.
// C[M,N] = A[M,K] @ W[K,N] + bias.
// OMODE 0: fp32 out; 1: tf32-bits out; 2: tf32-bits of 0.125*(acc+bias).
// 128x128 tile, 256 threads (8 warps, 64x32 each), k-tile 16.
// Dynamic smem: As 3x[128*APIT], Bs 3x[16*BPIT].
// ---------------------------------------------------------------------------
#define GEMM_SMEM ((3*128*APIT + 3*16*BPIT) * 4)   // 56832 B

template<int OMODE>
__global__ __launch_bounds__(256, 2)
void gemm_tf32(const uint32_t* __restrict__ A, const uint32_t* __restrict__ W,
               const float* __restrict__ bias, uint32_t* __restrict__ C,
               int M, int N, int K)
{
    extern __shared__ uint32_t gsm[];
    uint32_t* As = gsm;                      // 3 stages, 128*APIT each
    uint32_t* Bs = gsm + 3 * 128 * APIT;     // 3 stages, 16*BPIT each

    const int tid  = threadIdx.x;
    const int lane = tid & 31;
    const int wid  = tid >> 5;
    const int gi   = lane >> 2;
    const int tg   = lane & 3;
    const int m0   = (wid >> 2) * 64;
    const int n0   = (wid & 3) * 32;
    const int bm   = blockIdx.y * 128;
    const int bn   = blockIdx.x * 128;

    const int a_r = tid >> 2;              // 0..63 (and +64)
    const int a_o = (tid & 3) * 4;
    const int b_r = tid >> 5;              // 0..7 (and +8)
    const int b_o = (tid & 31) * 4;

    const uint32_t as_sa = (uint32_t)__cvta_generic_to_shared(As);
    const uint32_t bs_sa = (uint32_t)__cvta_generic_to_shared(Bs);

    float acc[4][4][4];
#pragma unroll
    for (int i = 0; i < 4; i++)
#pragma unroll
        for (int j = 0; j < 4; j++)
#pragma unroll
            for (int r = 0; r < 4; r++) acc[i][j][r] = 0.f;

    const int nkt = K / 16;

    // issue one k-tile into stage s
    auto issue = [&](int kt, int s) {
        const int ko = kt * 16;
        const uint32_t ab = as_sa + (uint32_t)(s * 128 * APIT * 4);
        const uint32_t bb = bs_sa + (uint32_t)(s * 16 * BPIT * 4);
        cp16(ab + (uint32_t)((a_r * APIT + a_o) * 4),
             A + (size_t)(bm + a_r) * K + ko + a_o);
        cp16(ab + (uint32_t)(((a_r + 64) * APIT + a_o) * 4),
             A + (size_t)(bm + a_r + 64) * K + ko + a_o);
        cp16(bb + (uint32_t)((b_r * BPIT + b_o) * 4),
             W + (size_t)(ko + b_r) * N + bn + b_o);
        cp16(bb + (uint32_t)(((b_r + 8) * BPIT + b_o) * 4),
             W + (size_t)(ko + b_r + 8) * N + bn + b_o);
        cp_commit();
    };

    issue(0, 0);
    issue(1, 1);

    for (int kt = 0; kt < nkt; kt++) {
        const int s = kt % 3;
        cp_wait_1();            // tile kt resident (kt+1 may still be in flight)
        __syncthreads();        // visibility + WAR vs compute of kt-1

        if (kt + 2 < nkt) issue(kt + 2, (kt + 2) % 3);

        const uint32_t* Ab = As + s * 128 * APIT;
        const uint32_t* Bb = Bs + s * 16 * BPIT;
#pragma unroll
        for (int ks = 0; ks < 2; ks++) {
            uint32_t af[4][4], bf[4][2];
#pragma unroll
            for (int mf = 0; mf < 4; mf++) {
                const uint32_t* p = &Ab[(m0 + 16*mf + gi) * APIT + 8*ks + tg];
                af[mf][0] = p[0];
                af[mf][1] = p[8 * APIT];
                af[mf][2] = p[4];
                af[mf][3] = p[8 * APIT + 4];
            }
#pragma unroll
            for (int nf = 0; nf < 4; nf++) {
                bf[nf][0] = Bb[(8*ks + tg) * BPIT + n0 + 8*nf + gi];
                bf[nf][1] = Bb[(8*ks + tg + 4) * BPIT + n0 + 8*nf + gi];
            }
#pragma unroll
            for (int mf = 0; mf < 4; mf++)
#pragma unroll
                for (int nf = 0; nf < 4; nf++)
                    mma_tf32(acc[mf][nf], af[mf], bf[nf]);
        }
    }

    // epilogue
#pragma unroll
    for (int mf = 0; mf < 4; mf++) {
        const int r0 = bm + m0 + 16*mf + gi;
        const int r1 = r0 + 8;
#pragma unroll
        for (int nf = 0; nf < 4; nf++) {
            const int c = bn + n0 + 8*nf + 2*tg;
            float2 bi = *(const float2*)&bias[c];
            float v00 = acc[mf][nf][0] + bi.x, v01 = acc[mf][nf][1] + bi.y;
            float v10 = acc[mf][nf][2] + bi.x, v11 = acc[mf][nf][3] + bi.y;
            if (OMODE == 0) {
                *(float2*)&((float*)C)[(size_t)r0 * N + c] = make_float2(v00, v01);
                *(float2*)&((float*)C)[(size_t)r1 * N + c] = make_float2(v10, v11);
            } else {
                if (OMODE == 2) { v00 *= 0.125f; v01 *= 0.125f; v10 *= 0.125f; v11 *= 0.125f; }
                *(uint2*)&C[(size_t)r0 * N + c] = make_uint2(f2tf32(v00), f2tf32(v01));
                *(uint2*)&C[(size_t)r1 * N + c] = make_uint2(f2tf32(v10), f2tf32(v11));
            }
        }
    }
}

// ---------------------------------------------------------------------------
// TF32 flash attention v5 = v3 structure (proven) + tf32-bit inputs +
// cp.async double-buffered K/V.
// One CTA per (qblock, head, batch), 128 threads, 4 warps; warp w owns
// query rows 16w..16w+15 -> softmax state & P tile warp-private.
// smem: qs/P [64][QP], ks 2x[64][QP], vs 2x[64][VP]  (89,088 B)
// ---------------------------------------------------------------------------
__global__ __launch_bounds__(128, 2)
void attn_tf32(const float* __restrict__ G)
{
    extern __shared__ uint32_t sm[];
    uint32_t* qs = sm;                               // Q staging then P
    uint32_t* ks = sm + 64 * QP;                     // 2 x [64][QP]
    uint32_t* vs = sm + 64 * QP + 2 * 64 * QP;       // 2 x [64][VP]
    __shared__ float kbuf[64];

    const int qb = blockIdx.x, h = blockIdx.y, b = blockIdx.z;
    const int tid  = threadIdx.x;
    const int lane = tid & 31;
    const int w    = tid >> 5;
    const int gi   = lane >> 2;
    const int tg   = lane & 3;

    // ---- keep check ----
    if (tid < 64) kbuf[tid] = fabsf(G[b * SEQ + qb * BLK + tid]);
    __syncthreads();
    float bmax = 0.f;
#pragma unroll
    for (int i = 0; i < 64; i++) bmax = fmaxf(bmax, kbuf[i]);

    if (bmax < 0.99f) {
        const uint4 z = make_uint4(0u, 0u, 0u, 0u);
#pragma unroll
        for (int i = 0; i < 8; i++) {
            int c = tid + i * 128;
            int r = c >> 4;
            int o = (c & 15) * 4;
            *(uint4*)&g_attn[(size_t)(b * SEQ + qb * BLK + r) * DMODEL + h * HDIM + o] = z;
        }
        return;
    }

    const uint32_t qs_sa = (uint32_t)__cvta_generic_to_shared(qs);
    const uint32_t ks_sa = (uint32_t)__cvta_generic_to_shared(ks);
    const uint32_t vs_sa = (uint32_t)__cvta_generic_to_shared(vs);

    // ---- prologue: Q (64x64) + K/V tile 0 via cp.async (one group) ----
#pragma unroll
    for (int i = 0; i < 8; i++) {                    // 1024 chunks each region
        int c = tid + i * 128;
        int r = c >> 4;
        int o = (c & 15) * 4;
        size_t qsrc = (size_t)(b * SEQ + qb * BLK + r) * DMODEL + h * HDIM + o;
        size_t ksrc = (size_t)(b * SEQ + r) * DMODEL + h * HDIM + o;
        cp16(qs_sa + (uint32_t)((r * QP + o) * 4), g_q + qsrc);
        cp16(ks_sa + (uint32_t)((r * QP + o) * 4), g_k + ksrc);
        cp16(vs_sa + (uint32_t)((r * VP + o) * 4), g_v + ksrc);
    }
    cp_commit();

    uint32_t qa[8][4];
    float o_[8][4];
#pragma unroll
    for (int nf = 0; nf < 8; nf++)
#pragma unroll
        for (int r = 0; r < 4; r++) o_[nf][r] = 0.f;
    float m0r = -1e30f, m1r = -1e30f, l0 = 0.f, l1 = 0.f;

    for (int kb = 0; kb < NB; kb++) {
        const int buf = kb & 1;
        cp_wait_all();
        __syncthreads();

        if (kb == 0) {
            // extract Q A-fragments (rows warp-private; P overwrites later)
#pragma unroll
            for (int k8 = 0; k8 < 8; k8++) {
                const uint32_t* q = &qs[(16*w + gi) * QP + 8*k8 + tg];
                qa[k8][0] = q[0];
                qa[k8][1] = q[8 * QP];
                qa[k8][2] = q[4];
                qa[k8][3] = q[8 * QP + 4];
            }
        }

        if (kb + 1 < NB) {
            const int nb2 = buf ^ 1;
            const uint32_t kd = ks_sa + (uint32_t)(nb2 * 64 * QP * 4);
            const uint32_t vd = vs_sa + (uint32_t)(nb2 * 64 * VP * 4);
#pragma unroll
            for (int i = 0; i < 8; i++) {
                int c = tid + i * 128;
                int r = c >> 4;
                int o = (c & 15) * 4;
                size_t src = (size_t)(b * SEQ + (kb + 1) * BLK + r) * DMODEL + h * HDIM + o;
                cp16(kd + (uint32_t)((r * QP + o) * 4), g_k + src);
                cp16(vd + (uint32_t)((r * VP + o) * 4), g_v + src);
            }
            cp_commit();
        }

        const uint32_t* ksb = ks + buf * 64 * QP;
        const uint32_t* vsb = vs + buf * 64 * VP;

        // ---- S = Q K^T : 16 rows x 64 key cols per warp ----
        float sc[8][4];
#pragma unroll
        for (int nf = 0; nf < 8; nf++)
            sc[nf][0] = sc[nf][1] = sc[nf][2] = sc[nf][3] = 0.f;
#pragma unroll
        for (int k8 = 0; k8 < 8; k8++)
#pragma unroll
            for (int nf = 0; nf < 8; nf++) {
                uint32_t bfr[2];
                bfr[0] = ksb[(8*nf + gi) * QP + 8*k8 + tg];
                bfr[1] = ksb[(8*nf + gi) * QP + 8*k8 + 4 + tg];
                mma_tf32(sc[nf], qa[k8], bfr);
            }

        // ---- online softmax (rows 16w+gi, 16w+gi+8; quad reduce) ----
        float mb0 = -1e30f, mb1 = -1e30f;
#pragma unroll
        for (int nf = 0; nf < 8; nf++) {
            mb0 = fmaxf(mb0, fmaxf(sc[nf][0], sc[nf][1]));
            mb1 = fmaxf(mb1, fmaxf(sc[nf][2], sc[nf][3]));
        }
        mb0 = fmaxf(mb0, __shfl_xor_sync(0xffffffffu, mb0, 1));
        mb0 = fmaxf(mb0, __shfl_xor_sync(0xffffffffu, mb0, 2));
        mb1 = fmaxf(mb1, __shfl_xor_sync(0xffffffffu, mb1, 1));
        mb1 = fmaxf(mb1, __shfl_xor_sync(0xffffffffu, mb1, 2));
        const float mn0 = fmaxf(m0r, mb0);
        const float mn1 = fmaxf(m1r, mb1);
        const float al0 = __expf(m0r - mn0);
        const float al1 = __expf(m1r - mn1);
        m0r = mn0; m1r = mn1;

        float s0 = 0.f, s1 = 0.f;
        const int pr0 = (16*w + gi) * QP;
        const int pr1 = pr0 + 8 * QP;
#pragma unroll
        for (int nf = 0; nf < 8; nf++) {
            float p0 = __expf(sc[nf][0] - mn0);
            float p1 = __expf(sc[nf][1] - mn0);
            float p2 = __expf(sc[nf][2] - mn1);
            float p3 = __expf(sc[nf][3] - mn1);
            s0 += p0 + p1;
            s1 += p2 + p3;
            const int c = 8*nf + 2*tg;
            *(uint2*)&qs[pr0 + c] = make_uint2(f2tf32(p0), f2tf32(p1));
            *(uint2*)&qs[pr1 + c] = make_uint2(f2tf32(p2), f2tf32(p3));
        }
        s0 += __shfl_xor_sync(0xffffffffu, s0, 1);
        s0 += __shfl_xor_sync(0xffffffffu, s0, 2);
        s1 += __shfl_xor_sync(0xffffffffu, s1, 1);
        s1 += __shfl_xor_sync(0xffffffffu, s1, 2);
        l0 = l0 * al0 + s0;
        l1 = l1 * al1 + s1;
#pragma unroll
        for (int nf = 0; nf < 8; nf++) {
            o_[nf][0] *= al0; o_[nf][1] *= al0;
            o_[nf][2] *= al1; o_[nf][3] *= al1;
        }
        __syncwarp();   // P rows warp-private: store->read ordering

        // ---- O += P V ----
#pragma unroll
        for (int k8 = 0; k8 < 8; k8++) {
            uint32_t pa[4];
            const uint32_t* pp = &qs[(16*w + gi) * QP + 8*k8 + tg];
            pa[0] = pp[0];
            pa[1] = pp[8 * QP];
            pa[2] = pp[4];
            pa[3] = pp[8 * QP + 4];
#pragma unroll
            for (int nf = 0; nf < 8; nf++) {
                uint32_t bfr[2];
                bfr[0] = vsb[(8*k8 + tg) * VP + 8*nf + gi];
                bfr[1] = vsb[(8*k8 + tg + 4) * VP + 8*nf + gi];
                mma_tf32(o_[nf], pa, bfr);
            }
        }
    }

    // ---- epilogue: write tf32 bits of O/l ----
    const float inv0 = 1.0f / l0;
    const float inv1 = 1.0f / l1;
    const size_t rb0 = (size_t)(b * SEQ + qb * BLK + 16*w + gi) * DMODEL + h * HDIM;
    const size_t rb1 = rb0 + (size_t)8 * DMODEL;
#pragma unroll
    for (int nf = 0; nf < 8; nf++) {
        const int c = 8*nf + 2*tg;
        *(uint2*)&g_attn[rb0 + c] = make_uint2(f2tf32(o_[nf][0] * inv0),
                                               f2tf32(o_[nf][1] * inv0));
        *(uint2*)&g_attn[rb1 + c] = make_uint2(f2tf32(o_[nf][2] * inv1),
                                               f2tf32(o_[nf][3] * inv1));
    }
}

// ---------------------------------------------------------------------------
extern "C" void kernel_launch(void* const* d_in, const int* in_sizes, int n_in,
                              void* d_out, int out_size)
{
    const float* x  = (const float*)d_in[0];
    const float* G  = (const float*)d_in[1];
    const float* Wq = (const float*)d_in[2];
    const float* bq = (const float*)d_in[3];
    const float* Wk = (const float*)d_in[4];
    const float* bk = (const float*)d_in[5];
    const float* Wv = (const float*)d_in[6];
    const float* bv = (const float*)d_in[7];
    const float* Wo = (const float*)d_in[8];
    const float* bo = (const float*)d_in[9];
    float* out = (float*)d_out;

    uint32_t *qp_, *kp_, *vp_, *ap_, *xt_, *wq_, *wk_, *wv_, *wo_;
    cudaGetSymbolAddress((void**)&qp_, g_q);
    cudaGetSymbolAddress((void**)&kp_, g_k);
    cudaGetSymbolAddress((void**)&vp_, g_v);
    cudaGetSymbolAddress((void**)&ap_, g_attn);
    cudaGetSymbolAddress((void**)&xt_, g_xt);
    cudaGetSymbolAddress((void**)&wq_, g_wq);
    cudaGetSymbolAddress((void**)&wk_, g_wk);
    cudaGetSymbolAddress((void**)&wv_, g_wv);
    cudaGetSymbolAddress((void**)&wo_, g_wo);

    // pre-convert inputs to tf32 bits
    const int xn4 = MROWS * DMODEL / 4;
    const int wn4 = DMODEL * DMODEL / 4;
    conv_tf32<<<(xn4 + 255) / 256, 256>>>((const float4*)x,  (uint4*)xt_, xn4);
    conv_tf32<<<(wn4 + 255) / 256, 256>>>((const float4*)Wq, (uint4*)wq_, wn4);
    conv_tf32<<<(wn4 + 255) / 256, 256>>>((const float4*)Wk, (uint4*)wk_, wn4);
    conv_tf32<<<(wn4 + 255) / 256, 256>>>((const float4*)Wv, (uint4*)wv_, wn4);
    conv_tf32<<<(wn4 + 255) / 256, 256>>>((const float4*)Wo, (uint4*)wo_, wn4);

    cudaFuncSetAttribute(gemm_tf32<0>, cudaFuncAttributeMaxDynamicSharedMemorySize, GEMM_SMEM);
    cudaFuncSetAttribute(gemm_tf32<1>, cudaFuncAttributeMaxDynamicSharedMemorySize, GEMM_SMEM);
    cudaFuncSetAttribute(gemm_tf32<2>, cudaFuncAttributeMaxDynamicSharedMemorySize, GEMM_SMEM);

    const dim3 gproj(DMODEL / 128, MROWS / 128);
    gemm_tf32<2><<<gproj, 256, GEMM_SMEM>>>(xt_, wq_, bq, qp_, MROWS, DMODEL, DMODEL);  // Q * 1/8
    gemm_tf32<1><<<gproj, 256, GEMM_SMEM>>>(xt_, wk_, bk, kp_, MROWS, DMODEL, DMODEL);
    gemm_tf32<1><<<gproj, 256, GEMM_SMEM>>>(xt_, wv_, bv, vp_, MROWS, DMODEL, DMODEL);

    const int attn_smem = (64 * QP + 2 * 64 * QP + 2 * 64 * VP) * (int)sizeof(uint32_t); // 89,088 B
    cudaFuncSetAttribute(attn_tf32, cudaFuncAttributeMaxDynamicSharedMemorySize, attn_smem);
    attn_tf32<<<dim3(NB, NHEADS, BATCH), 128, attn_smem>>>(G);

    gemm_tf32<0><<<gproj, 256, GEMM_SMEM>>>(ap_, wo_, bo, (uint32_t*)out, MROWS, DMODEL, DMODEL);
}

// round 14
// speedup vs baseline: 1.2161x; 1.0991x over previous
#include <cuda_runtime.h>
#include <math.h>
#include <stdint.h>

#define BATCH   2
#define SEQ     2048
#define DMODEL  1024
#define NHEADS  16
#define HDIM    64
#define BLK     64
#define NB      (SEQ/BLK)         // 32 blocks per batch
#define MROWS   (BATCH*SEQ)       // 4096

#define QP      68                // qs/ks pitch (words)
#define VP      72                // vs pitch (words)
#define APIT    20                // GEMM A smem pitch
#define BPIT    136               // GEMM B smem pitch

// Scratch (device globals: allocation-free, graph-capture safe).
__device__ __align__(16) uint32_t g_q[MROWS*DMODEL];
__device__ __align__(16) uint32_t g_k[MROWS*DMODEL];
__device__ __align__(16) uint32_t g_v[MROWS*DMODEL];
__device__ __align__(16) uint32_t g_attn[MROWS*DMODEL];
__device__ __align__(16) uint32_t g_xt[MROWS*DMODEL];      // x in tf32 bits
__device__ __align__(16) uint32_t g_wq[DMODEL*DMODEL];
__device__ __align__(16) uint32_t g_wk[DMODEL*DMODEL];
__device__ __align__(16) uint32_t g_wv[DMODEL*DMODEL];
__device__ __align__(16) uint32_t g_wo[DMODEL*DMODEL];

// ---------------------------------------------------------------------------
// helpers
// ---------------------------------------------------------------------------
__device__ __forceinline__ uint32_t f2tf32(float f) {
    uint32_t u;
    asm("cvt.rna.tf32.f32 %0, %1;" : "=r"(u) : "f"(f));
    return u;
}

__device__ __forceinline__ void mma_tf32(float* d, const uint32_t* a, const uint32_t* b) {
    asm volatile(
        "mma.sync.aligned.m16n8k8.row.col.f32.tf32.tf32.f32 "
        "{%0,%1,%2,%3}, {%4,%5,%6,%7}, {%8,%9}, {%0,%1,%2,%3};"
        : "+f"(d[0]), "+f"(d[1]), "+f"(d[2]), "+f"(d[3])
        : "r"(a[0]), "r"(a[1]), "r"(a[2]), "r"(a[3]),
          "r"(b[0]), "r"(b[1]));
}

__device__ __forceinline__ void cp16(uint32_t smem_addr, const void* gptr) {
    asm volatile("cp.async.cg.shared.global [%0], [%1], 16;\n"
                 :: "r"(smem_addr), "l"(gptr));
}
__device__ __forceinline__ void cp_commit() {
    asm volatile("cp.async.commit_group;\n" ::: "memory");
}
__device__ __forceinline__ void cp_wait_all() {
    asm volatile("cp.async.wait_group 0;\n" ::: "memory");
}
__device__ __forceinline__ void cp_wait_1() {
    asm volatile("cp.async.wait_group 1;\n" ::: "memory");
}

// ---------------------------------------------------------------------------
// fp32 -> tf32-bits conversion (x), and fused 4-weight variant
// ---------------------------------------------------------------------------
__global__ void conv_tf32(const float4* __restrict__ in, uint4* __restrict__ out, int n4)
{
    int i = blockIdx.x * blockDim.x + threadIdx.x;
    if (i < n4) {
        float4 v = in[i];
        out[i] = make_uint4(f2tf32(v.x), f2tf32(v.y), f2tf32(v.z), f2tf32(v.w));
    }
}

__global__ void conv_w4(const float4* w0, const float4* w1,
                        const float4* w2, const float4* w3, int n4)
{
    const float4* in;
    uint4* out;
    switch (blockIdx.y) {
        case 0:  in = w0; out = (uint4*)g_wq; break;
        case 1:  in = w1; out = (uint4*)g_wk; break;
        case 2:  in = w2; out = (uint4*)g_wv; break;
        default: in = w3; out = (uint4*)g_wo; break;
    }
    int i = blockIdx.x * blockDim.x + threadIdx.x;
    if (i < n4) {
        float4 v = in[i];
        out[i] = make_uint4(f2tf32(v.x), f2tf32(v.y), f2tf32(v.z), f2tf32(v.w));
    }
}

// ---------------------------------------------------------------------------
// GEMM core loop (3-stage cp.async pipeline), K = N = DMODEL.
// ---------------------------------------------------------------------------
#define GEMM_SMEM ((3*128*APIT + 3*16*BPIT) * 4)   // 56832 B

__device__ __forceinline__ void gemm_core(
    const uint32_t* __restrict__ A, const uint32_t* __restrict__ W,
    uint32_t* As, uint32_t* Bs, int bm, int bn,
    int tid, int m0, int n0, int gi, int tg, float acc[4][4][4])
{
    const int a_r = tid >> 2;
    const int a_o = (tid & 3) * 4;
    const int b_r = tid >> 5;
    const int b_o = (tid & 31) * 4;
    const int N = DMODEL, K = DMODEL;

    const uint32_t as_sa = (uint32_t)__cvta_generic_to_shared(As);
    const uint32_t bs_sa = (uint32_t)__cvta_generic_to_shared(Bs);

    auto issue = [&](int kt, int s) {
        const int ko = kt * 16;
        const uint32_t ab = as_sa + (uint32_t)(s * 128 * APIT * 4);
        const uint32_t bb = bs_sa + (uint32_t)(s * 16 * BPIT * 4);
        cp16(ab + (uint32_t)((a_r * APIT + a_o) * 4),
             A + (size_t)(bm + a_r) * K + ko + a_o);
        cp16(ab + (uint32_t)(((a_r + 64) * APIT + a_o) * 4),
             A + (size_t)(bm + a_r + 64) * K + ko + a_o);
        cp16(bb + (uint32_t)((b_r * BPIT + b_o) * 4),
             W + (size_t)(ko + b_r) * N + bn + b_o);
        cp16(bb + (uint32_t)(((b_r + 8) * BPIT + b_o) * 4),
             W + (size_t)(ko + b_r + 8) * N + bn + b_o);
        cp_commit();
    };

    const int nkt = K / 16;
    issue(0, 0);
    issue(1, 1);

    for (int kt = 0; kt < nkt; kt++) {
        const int s = kt % 3;
        cp_wait_1();
        __syncthreads();
        if (kt + 2 < nkt) issue(kt + 2, (kt + 2) % 3);

        const uint32_t* Ab = As + s * 128 * APIT;
        const uint32_t* Bb = Bs + s * 16 * BPIT;
#pragma unroll
        for (int ks = 0; ks < 2; ks++) {
            uint32_t af[4][4], bf[4][2];
#pragma unroll
            for (int mf = 0; mf < 4; mf++) {
                const uint32_t* p = &Ab[(m0 + 16*mf + gi) * APIT + 8*ks + tg];
                af[mf][0] = p[0];
                af[mf][1] = p[8 * APIT];
                af[mf][2] = p[4];
                af[mf][3] = p[8 * APIT + 4];
            }
#pragma unroll
            for (int nf = 0; nf < 4; nf++) {
                bf[nf][0] = Bb[(8*ks + tg) * BPIT + n0 + 8*nf + gi];
                bf[nf][1] = Bb[(8*ks + tg + 4) * BPIT + n0 + 8*nf + gi];
            }
#pragma unroll
            for (int mf = 0; mf < 4; mf++)
#pragma unroll
                for (int nf = 0; nf < 4; nf++)
                    mma_tf32(acc[mf][nf], af[mf], bf[nf]);
        }
    }
}

// ---------------------------------------------------------------------------
// Fused Q/K/V projection (grid.z = 0/1/2). NO keep-based skipping.
// z=0: Q (tf32 bits of 0.125*(acc+bias)); z=1: K; z=2: V (tf32 bits).
// ---------------------------------------------------------------------------
__global__ __launch_bounds__(256, 2)
void gemm_qkv(const uint32_t* __restrict__ A,
              const float* __restrict__ bq, const float* __restrict__ bk,
              const float* __restrict__ bv)
{
    const int z  = blockIdx.z;
    const int bm = blockIdx.y * 128;
    const int bn = blockIdx.x * 128;

    const uint32_t* W;
    const float* bias;
    uint32_t* C;
    if      (z == 0) { W = g_wq; bias = bq; C = g_q; }
    else if (z == 1) { W = g_wk; bias = bk; C = g_k; }
    else             { W = g_wv; bias = bv; C = g_v; }

    extern __shared__ uint32_t gsm[];
    uint32_t* As = gsm;
    uint32_t* Bs = gsm + 3 * 128 * APIT;

    const int tid  = threadIdx.x;
    const int lane = tid & 31;
    const int wid  = tid >> 5;
    const int gi   = lane >> 2;
    const int tg   = lane & 3;
    const int m0   = (wid >> 2) * 64;
    const int n0   = (wid & 3) * 32;

    float acc[4][4][4];
#pragma unroll
    for (int i = 0; i < 4; i++)
#pragma unroll
        for (int j = 0; j < 4; j++)
#pragma unroll
            for (int r = 0; r < 4; r++) acc[i][j][r] = 0.f;

    gemm_core(A, W, As, Bs, bm, bn, tid, m0, n0, gi, tg, acc);

#pragma unroll
    for (int mf = 0; mf < 4; mf++) {
        const int r0 = bm + m0 + 16*mf + gi;
        const int r1 = r0 + 8;
#pragma unroll
        for (int nf = 0; nf < 4; nf++) {
            const int c = bn + n0 + 8*nf + 2*tg;
            float2 bi = *(const float2*)&bias[c];
            float v00 = acc[mf][nf][0] + bi.x, v01 = acc[mf][nf][1] + bi.y;
            float v10 = acc[mf][nf][2] + bi.x, v11 = acc[mf][nf][3] + bi.y;
            if (z == 0) { v00 *= 0.125f; v01 *= 0.125f; v10 *= 0.125f; v11 *= 0.125f; }
            *(uint2*)&C[(size_t)r0 * DMODEL + c] = make_uint2(f2tf32(v00), f2tf32(v01));
            *(uint2*)&C[(size_t)r1 * DMODEL + c] = make_uint2(f2tf32(v10), f2tf32(v11));
        }
    }
}

// ---------------------------------------------------------------------------
// O projection: fp32 out. NO keep-based fast path (R10 semantics).
// ---------------------------------------------------------------------------
__global__ __launch_bounds__(256, 2)
void gemm_o(const uint32_t* __restrict__ A, const float* __restrict__ bias,
            float* __restrict__ C)
{
    const int bm = blockIdx.y * 128;
    const int bn = blockIdx.x * 128;

    extern __shared__ uint32_t gsm[];
    uint32_t* As = gsm;
    uint32_t* Bs = gsm + 3 * 128 * APIT;

    const int tid  = threadIdx.x;
    const int lane = tid & 31;
    const int wid  = tid >> 5;
    const int gi   = lane >> 2;
    const int tg   = lane & 3;
    const int m0   = (wid >> 2) * 64;
    const int n0   = (wid & 3) * 32;

    float acc[4][4][4];
#pragma unroll
    for (int i = 0; i < 4; i++)
#pragma unroll
        for (int j = 0; j < 4; j++)
#pragma unroll
            for (int r = 0; r < 4; r++) acc[i][j][r] = 0.f;

    gemm_core(A, g_wo, As, Bs, bm, bn, tid, m0, n0, gi, tg, acc);

#pragma unroll
    for (int mf = 0; mf < 4; mf++) {
        const int r0 = bm + m0 + 16*mf + gi;
        const int r1 = r0 + 8;
#pragma unroll
        for (int nf = 0; nf < 4; nf++) {
            const int c = bn + n0 + 8*nf + 2*tg;
            float2 bi = *(const float2*)&bias[c];
            *(float2*)&C[(size_t)r0 * DMODEL + c] =
                make_float2(acc[mf][nf][0] + bi.x, acc[mf][nf][1] + bi.y);
            *(float2*)&C[(size_t)r1 * DMODEL + c] =
                make_float2(acc[mf][nf][2] + bi.x, acc[mf][nf][3] + bi.y);
        }
    }
}

// ---------------------------------------------------------------------------
// TF32 flash attention (R10 version, verbatim): one CTA per (qblock, head,
// batch), 128 threads, 4 warps; warp w owns query rows 16w..16w+15.
// Computes its own keep check from G.
// ---------------------------------------------------------------------------
__global__ __launch_bounds__(128, 2)
void attn_tf32(const float* __restrict__ G)
{
    extern __shared__ uint32_t sm[];
    uint32_t* qs = sm;                               // Q staging then P
    uint32_t* ks = sm + 64 * QP;                     // 2 x [64][QP]
    uint32_t* vs = sm + 64 * QP + 2 * 64 * QP;       // 2 x [64][VP]
    __shared__ float kbuf[64];

    const int qb = blockIdx.x, h = blockIdx.y, b = blockIdx.z;
    const int tid  = threadIdx.x;
    const int lane = tid & 31;
    const int w    = tid >> 5;
    const int gi   = lane >> 2;
    const int tg   = lane & 3;

    // ---- keep check ----
    if (tid < 64) kbuf[tid] = fabsf(G[b * SEQ + qb * BLK + tid]);
    __syncthreads();
    float bmax = 0.f;
#pragma unroll
    for (int i = 0; i < 64; i++) bmax = fmaxf(bmax, kbuf[i]);

    if (bmax < 0.99f) {
        const uint4 z = make_uint4(0u, 0u, 0u, 0u);
#pragma unroll
        for (int i = 0; i < 8; i++) {
            int c = tid + i * 128;
            int r = c >> 4;
            int o = (c & 15) * 4;
            *(uint4*)&g_attn[(size_t)(b * SEQ + qb * BLK + r) * DMODEL + h * HDIM + o] = z;
        }
        return;
    }

    const uint32_t qs_sa = (uint32_t)__cvta_generic_to_shared(qs);
    const uint32_t ks_sa = (uint32_t)__cvta_generic_to_shared(ks);
    const uint32_t vs_sa = (uint32_t)__cvta_generic_to_shared(vs);

    // prologue: Q + K/V tile 0
#pragma unroll
    for (int i = 0; i < 8; i++) {
        int c = tid + i * 128;
        int r = c >> 4;
        int o = (c & 15) * 4;
        size_t qsrc = (size_t)(b * SEQ + qb * BLK + r) * DMODEL + h * HDIM + o;
        size_t ksrc = (size_t)(b * SEQ + r) * DMODEL + h * HDIM + o;
        cp16(qs_sa + (uint32_t)((r * QP + o) * 4), g_q + qsrc);
        cp16(ks_sa + (uint32_t)((r * QP + o) * 4), g_k + ksrc);
        cp16(vs_sa + (uint32_t)((r * VP + o) * 4), g_v + ksrc);
    }
    cp_commit();

    uint32_t qa[8][4];
    float o_[8][4];
#pragma unroll
    for (int nf = 0; nf < 8; nf++)
#pragma unroll
        for (int r = 0; r < 4; r++) o_[nf][r] = 0.f;
    float m0r = -1e30f, m1r = -1e30f, l0 = 0.f, l1 = 0.f;

    for (int kb = 0; kb < NB; kb++) {
        const int buf = kb & 1;
        cp_wait_all();
        __syncthreads();

        if (kb == 0) {
#pragma unroll
            for (int k8 = 0; k8 < 8; k8++) {
                const uint32_t* q = &qs[(16*w + gi) * QP + 8*k8 + tg];
                qa[k8][0] = q[0];
                qa[k8][1] = q[8 * QP];
                qa[k8][2] = q[4];
                qa[k8][3] = q[8 * QP + 4];
            }
        }

        if (kb + 1 < NB) {
            const int nb2 = buf ^ 1;
            const uint32_t kd = ks_sa + (uint32_t)(nb2 * 64 * QP * 4);
            const uint32_t vd = vs_sa + (uint32_t)(nb2 * 64 * VP * 4);
#pragma unroll
            for (int i = 0; i < 8; i++) {
                int c = tid + i * 128;
                int r = c >> 4;
                int o = (c & 15) * 4;
                size_t src = (size_t)(b * SEQ + (kb + 1) * BLK + r) * DMODEL + h * HDIM + o;
                cp16(kd + (uint32_t)((r * QP + o) * 4), g_k + src);
                cp16(vd + (uint32_t)((r * VP + o) * 4), g_v + src);
            }
            cp_commit();
        }

        const uint32_t* ksb = ks + buf * 64 * QP;
        const uint32_t* vsb = vs + buf * 64 * VP;

        float sc[8][4];
#pragma unroll
        for (int nf = 0; nf < 8; nf++)
            sc[nf][0] = sc[nf][1] = sc[nf][2] = sc[nf][3] = 0.f;
#pragma unroll
        for (int k8 = 0; k8 < 8; k8++)
#pragma unroll
            for (int nf = 0; nf < 8; nf++) {
                uint32_t bfr[2];
                bfr[0] = ksb[(8*nf + gi) * QP + 8*k8 + tg];
                bfr[1] = ksb[(8*nf + gi) * QP + 8*k8 + 4 + tg];
                mma_tf32(sc[nf], qa[k8], bfr);
            }

        float mb0 = -1e30f, mb1 = -1e30f;
#pragma unroll
        for (int nf = 0; nf < 8; nf++) {
            mb0 = fmaxf(mb0, fmaxf(sc[nf][0], sc[nf][1]));
            mb1 = fmaxf(mb1, fmaxf(sc[nf][2], sc[nf][3]));
        }
        mb0 = fmaxf(mb0, __shfl_xor_sync(0xffffffffu, mb0, 1));
        mb0 = fmaxf(mb0, __shfl_xor_sync(0xffffffffu, mb0, 2));
        mb1 = fmaxf(mb1, __shfl_xor_sync(0xffffffffu, mb1, 1));
        mb1 = fmaxf(mb1, __shfl_xor_sync(0xffffffffu, mb1, 2));
        const float mn0 = fmaxf(m0r, mb0);
        const float mn1 = fmaxf(m1r, mb1);
        const float al0 = __expf(m0r - mn0);
        const float al1 = __expf(m1r - mn1);
        m0r = mn0; m1r = mn1;

        float s0 = 0.f, s1 = 0.f;
        const int pr0 = (16*w + gi) * QP;
        const int pr1 = pr0 + 8 * QP;
#pragma unroll
        for (int nf = 0; nf < 8; nf++) {
            float p0 = __expf(sc[nf][0] - mn0);
            float p1 = __expf(sc[nf][1] - mn0);
            float p2 = __expf(sc[nf][2] - mn1);
            float p3 = __expf(sc[nf][3] - mn1);
            s0 += p0 + p1;
            s1 += p2 + p3;
            const int c = 8*nf + 2*tg;
            *(uint2*)&qs[pr0 + c] = make_uint2(f2tf32(p0), f2tf32(p1));
            *(uint2*)&qs[pr1 + c] = make_uint2(f2tf32(p2), f2tf32(p3));
        }
        s0 += __shfl_xor_sync(0xffffffffu, s0, 1);
        s0 += __shfl_xor_sync(0xffffffffu, s0, 2);
        s1 += __shfl_xor_sync(0xffffffffu, s1, 1);
        s1 += __shfl_xor_sync(0xffffffffu, s1, 2);
        l0 = l0 * al0 + s0;
        l1 = l1 * al1 + s1;
#pragma unroll
        for (int nf = 0; nf < 8; nf++) {
            o_[nf][0] *= al0; o_[nf][1] *= al0;
            o_[nf][2] *= al1; o_[nf][3] *= al1;
        }
        __syncwarp();

#pragma unroll
        for (int k8 = 0; k8 < 8; k8++) {
            uint32_t pa[4];
            const uint32_t* pp = &qs[(16*w + gi) * QP + 8*k8 + tg];
            pa[0] = pp[0];
            pa[1] = pp[8 * QP];
            pa[2] = pp[4];
            pa[3] = pp[8 * QP + 4];
#pragma unroll
            for (int nf = 0; nf < 8; nf++) {
                uint32_t bfr[2];
                bfr[0] = vsb[(8*k8 + tg) * VP + 8*nf + gi];
                bfr[1] = vsb[(8*k8 + tg + 4) * VP + 8*nf + gi];
                mma_tf32(o_[nf], pa, bfr);
            }
        }
    }

    const float inv0 = 1.0f / l0;
    const float inv1 = 1.0f / l1;
    const size_t rb0 = (size_t)(b * SEQ + qb * BLK + 16*w + gi) * DMODEL + h * HDIM;
    const size_t rb1 = rb0 + (size_t)8 * DMODEL;
#pragma unroll
    for (int nf = 0; nf < 8; nf++) {
        const int c = 8*nf + 2*tg;
        *(uint2*)&g_attn[rb0 + c] = make_uint2(f2tf32(o_[nf][0] * inv0),
                                               f2tf32(o_[nf][1] * inv0));
        *(uint2*)&g_attn[rb1 + c] = make_uint2(f2tf32(o_[nf][2] * inv1),
                                               f2tf32(o_[nf][3] * inv1));
    }
}

// ---------------------------------------------------------------------------
extern "C" void kernel_launch(void* const* d_in, const int* in_sizes, int n_in,
                              void* d_out, int out_size)
{
    const float* x  = (const float*)d_in[0];
    const float* G  = (const float*)d_in[1];
    const float* Wq = (const float*)d_in[2];
    const float* bq = (const float*)d_in[3];
    const float* Wk = (const float*)d_in[4];
    const float* bk = (const float*)d_in[5];
    const float* Wv = (const float*)d_in[6];
    const float* bv = (const float*)d_in[7];
    const float* Wo = (const float*)d_in[8];
    const float* bo = (const float*)d_in[9];
    float* out = (float*)d_out;

    uint32_t *ap_, *xt_;
    cudaGetSymbolAddress((void**)&ap_, g_attn);
    cudaGetSymbolAddress((void**)&xt_, g_xt);

    // tf32 pre-conversion (x + fused 4 weights)
    const int xn4 = MROWS * DMODEL / 4;
    const int wn4 = DMODEL * DMODEL / 4;
    conv_tf32<<<(xn4 + 255) / 256, 256>>>((const float4*)x, (uint4*)xt_, xn4);
    conv_w4<<<dim3((wn4 + 255) / 256, 4), 256>>>((const float4*)Wq, (const float4*)Wk,
                                                 (const float4*)Wv, (const float4*)Wo, wn4);

    cudaFuncSetAttribute(gemm_qkv, cudaFuncAttributeMaxDynamicSharedMemorySize, GEMM_SMEM);
    cudaFuncSetAttribute(gemm_o,   cudaFuncAttributeMaxDynamicSharedMemorySize, GEMM_SMEM);

    // fused Q/K/V projections (no keep-based skipping)
    gemm_qkv<<<dim3(DMODEL / 128, MROWS / 128, 3), 256, GEMM_SMEM>>>(xt_, bq, bk, bv);

    // attention (computes keep masks itself, R10 semantics)
    const int attn_smem = (64 * QP + 2 * 64 * QP + 2 * 64 * VP) * (int)sizeof(uint32_t); // 89,088 B
    cudaFuncSetAttribute(attn_tf32, cudaFuncAttributeMaxDynamicSharedMemorySize, attn_smem);
    attn_tf32<<<dim3(NB, NHEADS, BATCH), 128, attn_smem>>>(G);

    // O projection (full, no fast path)
    gemm_o<<<dim3(DMODEL / 128, MROWS / 128), 256, GEMM_SMEM>>>(ap_, bo, out);
}

// round 15
// speedup vs baseline: 1.2173x; 1.0010x over previous
#include <cuda_runtime.h>
#include <math.h>
#include <stdint.h>

#define BATCH   2
#define SEQ     2048
#define DMODEL  1024
#define NHEADS  16
#define HDIM    64
#define BLK     64
#define NB      (SEQ/BLK)         // 32 blocks per batch
#define MROWS   (BATCH*SEQ)       // 4096

#define QP      68                // qs/ks pitch (words)
#define VP      72                // vs pitch (words); cols 64..71 = ones column pad
#define APIT    20                // GEMM A smem pitch
#define BPIT    136               // GEMM B smem pitch

// Q scale folded with log2(e): softmax runs in exp2 domain.
#define QSCALE  0.18033688011112042f   // 0.125 * log2(e)

// Scratch (device globals: allocation-free, graph-capture safe).
__device__ __align__(16) uint32_t g_q[MROWS*DMODEL];
__device__ __align__(16) uint32_t g_k[MROWS*DMODEL];
__device__ __align__(16) uint32_t g_v[MROWS*DMODEL];
__device__ __align__(16) uint32_t g_attn[MROWS*DMODEL];
__device__ __align__(16) uint32_t g_xt[MROWS*DMODEL];      // x in tf32 bits
__device__ __align__(16) uint32_t g_wq[DMODEL*DMODEL];
__device__ __align__(16) uint32_t g_wk[DMODEL*DMODEL];
__device__ __align__(16) uint32_t g_wv[DMODEL*DMODEL];
__device__ __align__(16) uint32_t g_wo[DMODEL*DMODEL];

// ---------------------------------------------------------------------------
// helpers
// ---------------------------------------------------------------------------
__device__ __forceinline__ uint32_t f2tf32(float f) {
    uint32_t u;
    asm("cvt.rna.tf32.f32 %0, %1;" : "=r"(u) : "f"(f));
    return u;
}

__device__ __forceinline__ void mma_tf32(float* d, const uint32_t* a, const uint32_t* b) {
    asm volatile(
        "mma.sync.aligned.m16n8k8.row.col.f32.tf32.tf32.f32 "
        "{%0,%1,%2,%3}, {%4,%5,%6,%7}, {%8,%9}, {%0,%1,%2,%3};"
        : "+f"(d[0]), "+f"(d[1]), "+f"(d[2]), "+f"(d[3])
        : "r"(a[0]), "r"(a[1]), "r"(a[2]), "r"(a[3]),
          "r"(b[0]), "r"(b[1]));
}

__device__ __forceinline__ void cp16(uint32_t smem_addr, const void* gptr) {
    asm volatile("cp.async.cg.shared.global [%0], [%1], 16;\n"
                 :: "r"(smem_addr), "l"(gptr));
}
__device__ __forceinline__ void cp_commit() {
    asm volatile("cp.async.commit_group;\n" ::: "memory");
}
__device__ __forceinline__ void cp_wait_all() {
    asm volatile("cp.async.wait_group 0;\n" ::: "memory");
}
__device__ __forceinline__ void cp_wait_1() {
    asm volatile("cp.async.wait_group 1;\n" ::: "memory");
}

// ---------------------------------------------------------------------------
// fp32 -> tf32-bits conversion (x), and fused 4-weight variant
// ---------------------------------------------------------------------------
__global__ void conv_tf32(const float4* __restrict__ in, uint4* __restrict__ out, int n4)
{
    int i = blockIdx.x * blockDim.x + threadIdx.x;
    if (i < n4) {
        float4 v = in[i];
        out[i] = make_uint4(f2tf32(v.x), f2tf32(v.y), f2tf32(v.z), f2tf32(v.w));
    }
}

__global__ void conv_w4(const float4* w0, const float4* w1,
                        const float4* w2, const float4* w3, int n4)
{
    const float4* in;
    uint4* out;
    switch (blockIdx.y) {
        case 0:  in = w0; out = (uint4*)g_wq; break;
        case 1:  in = w1; out = (uint4*)g_wk; break;
        case 2:  in = w2; out = (uint4*)g_wv; break;
        default: in = w3; out = (uint4*)g_wo; break;
    }
    int i = blockIdx.x * blockDim.x + threadIdx.x;
    if (i < n4) {
        float4 v = in[i];
        out[i] = make_uint4(f2tf32(v.x), f2tf32(v.y), f2tf32(v.z), f2tf32(v.w));
    }
}

// ---------------------------------------------------------------------------
// GEMM core loop (3-stage cp.async pipeline), K = N = DMODEL.
// ---------------------------------------------------------------------------
#define GEMM_SMEM ((3*128*APIT + 3*16*BPIT) * 4)   // 56832 B

__device__ __forceinline__ void gemm_core(
    const uint32_t* __restrict__ A, const uint32_t* __restrict__ W,
    uint32_t* As, uint32_t* Bs, int bm, int bn,
    int tid, int m0, int n0, int gi, int tg, float acc[4][4][4])
{
    const int a_r = tid >> 2;
    const int a_o = (tid & 3) * 4;
    const int b_r = tid >> 5;
    const int b_o = (tid & 31) * 4;
    const int N = DMODEL, K = DMODEL;

    const uint32_t as_sa = (uint32_t)__cvta_generic_to_shared(As);
    const uint32_t bs_sa = (uint32_t)__cvta_generic_to_shared(Bs);

    auto issue = [&](int kt, int s) {
        const int ko = kt * 16;
        const uint32_t ab = as_sa + (uint32_t)(s * 128 * APIT * 4);
        const uint32_t bb = bs_sa + (uint32_t)(s * 16 * BPIT * 4);
        cp16(ab + (uint32_t)((a_r * APIT + a_o) * 4),
             A + (size_t)(bm + a_r) * K + ko + a_o);
        cp16(ab + (uint32_t)(((a_r + 64) * APIT + a_o) * 4),
             A + (size_t)(bm + a_r + 64) * K + ko + a_o);
        cp16(bb + (uint32_t)((b_r * BPIT + b_o) * 4),
             W + (size_t)(ko + b_r) * N + bn + b_o);
        cp16(bb + (uint32_t)(((b_r + 8) * BPIT + b_o) * 4),
             W + (size_t)(ko + b_r + 8) * N + bn + b_o);
        cp_commit();
    };

    const int nkt = K / 16;
    issue(0, 0);
    issue(1, 1);

    for (int kt = 0; kt < nkt; kt++) {
        const int s = kt % 3;
        cp_wait_1();
        __syncthreads();
        if (kt + 2 < nkt) issue(kt + 2, (kt + 2) % 3);

        const uint32_t* Ab = As + s * 128 * APIT;
        const uint32_t* Bb = Bs + s * 16 * BPIT;
#pragma unroll
        for (int ks = 0; ks < 2; ks++) {
            uint32_t af[4][4], bf[4][2];
#pragma unroll
            for (int mf = 0; mf < 4; mf++) {
                const uint32_t* p = &Ab[(m0 + 16*mf + gi) * APIT + 8*ks + tg];
                af[mf][0] = p[0];
                af[mf][1] = p[8 * APIT];
                af[mf][2] = p[4];
                af[mf][3] = p[8 * APIT + 4];
            }
#pragma unroll
            for (int nf = 0; nf < 4; nf++) {
                bf[nf][0] = Bb[(8*ks + tg) * BPIT + n0 + 8*nf + gi];
                bf[nf][1] = Bb[(8*ks + tg + 4) * BPIT + n0 + 8*nf + gi];
            }
#pragma unroll
            for (int mf = 0; mf < 4; mf++)
#pragma unroll
                for (int nf = 0; nf < 4; nf++)
                    mma_tf32(acc[mf][nf], af[mf], bf[nf]);
        }
    }
}

// ---------------------------------------------------------------------------
// Fused Q/K/V projection (grid.z = 0/1/2). No keep-based skipping.
// z=0: Q (tf32 bits of QSCALE*(acc+bias)); z=1: K; z=2: V (tf32 bits).
// ---------------------------------------------------------------------------
__global__ __launch_bounds__(256, 2)
void gemm_qkv(const uint32_t* __restrict__ A,
              const float* __restrict__ bq, const float* __restrict__ bk,
              const float* __restrict__ bv)
{
    const int z  = blockIdx.z;
    const int bm = blockIdx.y * 128;
    const int bn = blockIdx.x * 128;

    const uint32_t* W;
    const float* bias;
    uint32_t* C;
    if      (z == 0) { W = g_wq; bias = bq; C = g_q; }
    else if (z == 1) { W = g_wk; bias = bk; C = g_k; }
    else             { W = g_wv; bias = bv; C = g_v; }

    extern __shared__ uint32_t gsm[];
    uint32_t* As = gsm;
    uint32_t* Bs = gsm + 3 * 128 * APIT;

    const int tid  = threadIdx.x;
    const int lane = tid & 31;
    const int wid  = tid >> 5;
    const int gi   = lane >> 2;
    const int tg   = lane & 3;
    const int m0   = (wid >> 2) * 64;
    const int n0   = (wid & 3) * 32;

    float acc[4][4][4];
#pragma unroll
    for (int i = 0; i < 4; i++)
#pragma unroll
        for (int j = 0; j < 4; j++)
#pragma unroll
            for (int r = 0; r < 4; r++) acc[i][j][r] = 0.f;

    gemm_core(A, W, As, Bs, bm, bn, tid, m0, n0, gi, tg, acc);

#pragma unroll
    for (int mf = 0; mf < 4; mf++) {
        const int r0 = bm + m0 + 16*mf + gi;
        const int r1 = r0 + 8;
#pragma unroll
        for (int nf = 0; nf < 4; nf++) {
            const int c = bn + n0 + 8*nf + 2*tg;
            float2 bi = *(const float2*)&bias[c];
            float v00 = acc[mf][nf][0] + bi.x, v01 = acc[mf][nf][1] + bi.y;
            float v10 = acc[mf][nf][2] + bi.x, v11 = acc[mf][nf][3] + bi.y;
            if (z == 0) { v00 *= QSCALE; v01 *= QSCALE; v10 *= QSCALE; v11 *= QSCALE; }
            *(uint2*)&C[(size_t)r0 * DMODEL + c] = make_uint2(f2tf32(v00), f2tf32(v01));
            *(uint2*)&C[(size_t)r1 * DMODEL + c] = make_uint2(f2tf32(v10), f2tf32(v11));
        }
    }
}

// ---------------------------------------------------------------------------
// O projection: fp32 out. Full (no keep fast path).
// ---------------------------------------------------------------------------
__global__ __launch_bounds__(256, 2)
void gemm_o(const uint32_t* __restrict__ A, const float* __restrict__ bias,
            float* __restrict__ C)
{
    const int bm = blockIdx.y * 128;
    const int bn = blockIdx.x * 128;

    extern __shared__ uint32_t gsm[];
    uint32_t* As = gsm;
    uint32_t* Bs = gsm + 3 * 128 * APIT;

    const int tid  = threadIdx.x;
    const int lane = tid & 31;
    const int wid  = tid >> 5;
    const int gi   = lane >> 2;
    const int tg   = lane & 3;
    const int m0   = (wid >> 2) * 64;
    const int n0   = (wid & 3) * 32;

    float acc[4][4][4];
#pragma unroll
    for (int i = 0; i < 4; i++)
#pragma unroll
        for (int j = 0; j < 4; j++)
#pragma unroll
            for (int r = 0; r < 4; r++) acc[i][j][r] = 0.f;

    gemm_core(A, g_wo, As, Bs, bm, bn, tid, m0, n0, gi, tg, acc);

#pragma unroll
    for (int mf = 0; mf < 4; mf++) {
        const int r0 = bm + m0 + 16*mf + gi;
        const int r1 = r0 + 8;
#pragma unroll
        for (int nf = 0; nf < 4; nf++) {
            const int c = bn + n0 + 8*nf + 2*tg;
            float2 bi = *(const float2*)&bias[c];
            *(float2*)&C[(size_t)r0 * DMODEL + c] =
                make_float2(acc[mf][nf][0] + bi.x, acc[mf][nf][1] + bi.y);
            *(float2*)&C[(size_t)r1 * DMODEL + c] =
                make_float2(acc[mf][nf][2] + bi.x, acc[mf][nf][3] + bi.y);
        }
    }
}

// ---------------------------------------------------------------------------
// TF32 flash attention v6: exp2-domain softmax + row-sum-via-mma.
// One CTA per (qblock, head, batch), 128 threads, 4 warps; warp w owns query
// rows 16w..16w+15. V tile carries a ones-column at smem col 64, so the
// softmax denominator l obeys the same rescale recurrence as O and falls out
// of PV as an extra output column (no per-tile sum shuffles).
// ---------------------------------------------------------------------------
__global__ __launch_bounds__(128, 2)
void attn_tf32(const float* __restrict__ G)
{
    extern __shared__ uint32_t sm[];
    uint32_t* qs = sm;                               // Q staging then P
    uint32_t* ks = sm + 64 * QP;                     // 2 x [64][QP]
    uint32_t* vs = sm + 64 * QP + 2 * 64 * QP;       // 2 x [64][VP]
    __shared__ float kbuf[64];

    const int qb = blockIdx.x, h = blockIdx.y, b = blockIdx.z;
    const int tid  = threadIdx.x;
    const int lane = tid & 31;
    const int w    = tid >> 5;
    const int gi   = lane >> 2;
    const int tg   = lane & 3;

    // ---- keep check ----
    if (tid < 64) kbuf[tid] = fabsf(G[b * SEQ + qb * BLK + tid]);
    __syncthreads();
    float bmax = 0.f;
#pragma unroll
    for (int i = 0; i < 64; i++) bmax = fmaxf(bmax, kbuf[i]);

    if (bmax < 0.99f) {
        const uint4 z = make_uint4(0u, 0u, 0u, 0u);
#pragma unroll
        for (int i = 0; i < 8; i++) {
            int c = tid + i * 128;
            int r = c >> 4;
            int o = (c & 15) * 4;
            *(uint4*)&g_attn[(size_t)(b * SEQ + qb * BLK + r) * DMODEL + h * HDIM + o] = z;
        }
        return;
    }

    // ---- one-time ones-column init for BOTH V buffers (cols 64..71) ----
    // cp.async loaders only touch cols 0..63, so this never races.
    {
        uint32_t* p = &vs[tid * VP + 64];        // rows 0..127 span both buffers
        *(uint4*)p       = make_uint4(0x3F800000u, 0u, 0u, 0u);  // 1.0, 0, 0, 0
        *(uint4*)(p + 4) = make_uint4(0u, 0u, 0u, 0u);
    }

    const uint32_t qs_sa = (uint32_t)__cvta_generic_to_shared(qs);
    const uint32_t ks_sa = (uint32_t)__cvta_generic_to_shared(ks);
    const uint32_t vs_sa = (uint32_t)__cvta_generic_to_shared(vs);

    // prologue: Q + K/V tile 0
#pragma unroll
    for (int i = 0; i < 8; i++) {
        int c = tid + i * 128;
        int r = c >> 4;
        int o = (c & 15) * 4;
        size_t qsrc = (size_t)(b * SEQ + qb * BLK + r) * DMODEL + h * HDIM + o;
        size_t ksrc = (size_t)(b * SEQ + r) * DMODEL + h * HDIM + o;
        cp16(qs_sa + (uint32_t)((r * QP + o) * 4), g_q + qsrc);
        cp16(ks_sa + (uint32_t)((r * QP + o) * 4), g_k + ksrc);
        cp16(vs_sa + (uint32_t)((r * VP + o) * 4), g_v + ksrc);
    }
    cp_commit();

    uint32_t qa[8][4];
    float o_[8][4];
    float lacc[4] = {0.f, 0.f, 0.f, 0.f};            // l via ones-column of V
#pragma unroll
    for (int nf = 0; nf < 8; nf++)
#pragma unroll
        for (int r = 0; r < 4; r++) o_[nf][r] = 0.f;
    float m0r = -1e30f, m1r = -1e30f;

    for (int kb = 0; kb < NB; kb++) {
        const int buf = kb & 1;
        cp_wait_all();
        __syncthreads();

        if (kb == 0) {
#pragma unroll
            for (int k8 = 0; k8 < 8; k8++) {
                const uint32_t* q = &qs[(16*w + gi) * QP + 8*k8 + tg];
                qa[k8][0] = q[0];
                qa[k8][1] = q[8 * QP];
                qa[k8][2] = q[4];
                qa[k8][3] = q[8 * QP + 4];
            }
        }

        if (kb + 1 < NB) {
            const int nb2 = buf ^ 1;
            const uint32_t kd = ks_sa + (uint32_t)(nb2 * 64 * QP * 4);
            const uint32_t vd = vs_sa + (uint32_t)(nb2 * 64 * VP * 4);
#pragma unroll
            for (int i = 0; i < 8; i++) {
                int c = tid + i * 128;
                int r = c >> 4;
                int o = (c & 15) * 4;
                size_t src = (size_t)(b * SEQ + (kb + 1) * BLK + r) * DMODEL + h * HDIM + o;
                cp16(kd + (uint32_t)((r * QP + o) * 4), g_k + src);
                cp16(vd + (uint32_t)((r * VP + o) * 4), g_v + src);
            }
            cp_commit();
        }

        const uint32_t* ksb = ks + buf * 64 * QP;
        const uint32_t* vsb = vs + buf * 64 * VP;

        // ---- S = Q K^T (scores already in log2 domain via QSCALE) ----
        float sc[8][4];
#pragma unroll
        for (int nf = 0; nf < 8; nf++)
            sc[nf][0] = sc[nf][1] = sc[nf][2] = sc[nf][3] = 0.f;
#pragma unroll
        for (int k8 = 0; k8 < 8; k8++)
#pragma unroll
            for (int nf = 0; nf < 8; nf++) {
                uint32_t bfr[2];
                bfr[0] = ksb[(8*nf + gi) * QP + 8*k8 + tg];
                bfr[1] = ksb[(8*nf + gi) * QP + 8*k8 + 4 + tg];
                mma_tf32(sc[nf], qa[k8], bfr);
            }

        // ---- online softmax: max-reduce only (sum comes from PV) ----
        float mb0 = -1e30f, mb1 = -1e30f;
#pragma unroll
        for (int nf = 0; nf < 8; nf++) {
            mb0 = fmaxf(mb0, fmaxf(sc[nf][0], sc[nf][1]));
            mb1 = fmaxf(mb1, fmaxf(sc[nf][2], sc[nf][3]));
        }
        mb0 = fmaxf(mb0, __shfl_xor_sync(0xffffffffu, mb0, 1));
        mb0 = fmaxf(mb0, __shfl_xor_sync(0xffffffffu, mb0, 2));
        mb1 = fmaxf(mb1, __shfl_xor_sync(0xffffffffu, mb1, 1));
        mb1 = fmaxf(mb1, __shfl_xor_sync(0xffffffffu, mb1, 2));
        const float mn0 = fmaxf(m0r, mb0);
        const float mn1 = fmaxf(m1r, mb1);
        const float al0 = exp2f(m0r - mn0);
        const float al1 = exp2f(m1r - mn1);
        m0r = mn0; m1r = mn1;

        const int pr0 = (16*w + gi) * QP;
        const int pr1 = pr0 + 8 * QP;
#pragma unroll
        for (int nf = 0; nf < 8; nf++) {
            float p0 = exp2f(sc[nf][0] - mn0);
            float p1 = exp2f(sc[nf][1] - mn0);
            float p2 = exp2f(sc[nf][2] - mn1);
            float p3 = exp2f(sc[nf][3] - mn1);
            const int c = 8*nf + 2*tg;
            *(uint2*)&qs[pr0 + c] = make_uint2(f2tf32(p0), f2tf32(p1));
            *(uint2*)&qs[pr1 + c] = make_uint2(f2tf32(p2), f2tf32(p3));
        }
#pragma unroll
        for (int nf = 0; nf < 8; nf++) {
            o_[nf][0] *= al0; o_[nf][1] *= al0;
            o_[nf][2] *= al1; o_[nf][3] *= al1;
        }
        lacc[0] *= al0; lacc[1] *= al0;
        lacc[2] *= al1; lacc[3] *= al1;
        __syncwarp();   // P rows warp-private: store->read ordering

        // ---- O += P V ; l += P @ ones (V col 64) ----
#pragma unroll
        for (int k8 = 0; k8 < 8; k8++) {
            uint32_t pa[4];
            const uint32_t* pp = &qs[(16*w + gi) * QP + 8*k8 + tg];
            pa[0] = pp[0];
            pa[1] = pp[8 * QP];
            pa[2] = pp[4];
            pa[3] = pp[8 * QP + 4];
#pragma unroll
            for (int nf = 0; nf < 8; nf++) {
                uint32_t bfr[2];
                bfr[0] = vsb[(8*k8 + tg) * VP + 8*nf + gi];
                bfr[1] = vsb[(8*k8 + tg + 4) * VP + 8*nf + gi];
                mma_tf32(o_[nf], pa, bfr);
            }
            {   // ones-column group (cols 64..71; col 64 = 1.0, rest 0)
                uint32_t bfr[2];
                bfr[0] = vsb[(8*k8 + tg) * VP + 64 + gi];
                bfr[1] = vsb[(8*k8 + tg + 4) * VP + 64 + gi];
                mma_tf32(lacc, pa, bfr);
            }
        }
    }

    // ---- epilogue: l lives in tg=0 lanes (col 64 = local col 0) ----
    const float l0 = __shfl_sync(0xffffffffu, lacc[0], lane & ~3);
    const float l1 = __shfl_sync(0xffffffffu, lacc[2], lane & ~3);
    const float inv0 = 1.0f / l0;
    const float inv1 = 1.0f / l1;
    const size_t rb0 = (size_t)(b * SEQ + qb * BLK + 16*w + gi) * DMODEL + h * HDIM;
    const size_t rb1 = rb0 + (size_t)8 * DMODEL;
#pragma unroll
    for (int nf = 0; nf < 8; nf++) {
        const int c = 8*nf + 2*tg;
        *(uint2*)&g_attn[rb0 + c] = make_uint2(f2tf32(o_[nf][0] * inv0),
                                               f2tf32(o_[nf][1] * inv0));
        *(uint2*)&g_attn[rb1 + c] = make_uint2(f2tf32(o_[nf][2] * inv1),
                                               f2tf32(o_[nf][3] * inv1));
    }
}

// ---------------------------------------------------------------------------
extern "C" void kernel_launch(void* const* d_in, const int* in_sizes, int n_in,
                              void* d_out, int out_size)
{
    const float* x  = (const float*)d_in[0];
    const float* G  = (const float*)d_in[1];
    const float* Wq = (const float*)d_in[2];
    const float* bq = (const float*)d_in[3];
    const float* Wk = (const float*)d_in[4];
    const float* bk = (const float*)d_in[5];
    const float* Wv = (const float*)d_in[6];
    const float* bv = (const float*)d_in[7];
    const float* Wo = (const float*)d_in[8];
    const float* bo = (const float*)d_in[9];
    float* out = (float*)d_out;

    uint32_t *ap_, *xt_;
    cudaGetSymbolAddress((void**)&ap_, g_attn);
    cudaGetSymbolAddress((void**)&xt_, g_xt);

    // tf32 pre-conversion (x + fused 4 weights)
    const int xn4 = MROWS * DMODEL / 4;
    const int wn4 = DMODEL * DMODEL / 4;
    conv_tf32<<<(xn4 + 255) / 256, 256>>>((const float4*)x, (uint4*)xt_, xn4);
    conv_w4<<<dim3((wn4 + 255) / 256, 4), 256>>>((const float4*)Wq, (const float4*)Wk,
                                                 (const float4*)Wv, (const float4*)Wo, wn4);

    cudaFuncSetAttribute(gemm_qkv, cudaFuncAttributeMaxDynamicSharedMemorySize, GEMM_SMEM);
    cudaFuncSetAttribute(gemm_o,   cudaFuncAttributeMaxDynamicSharedMemorySize, GEMM_SMEM);

    // fused Q/K/V projections
    gemm_qkv<<<dim3(DMODEL / 128, MROWS / 128, 3), 256, GEMM_SMEM>>>(xt_, bq, bk, bv);

    // attention
    const int attn_smem = (64 * QP + 2 * 64 * QP + 2 * 64 * VP) * (int)sizeof(uint32_t); // 89,088 B
    cudaFuncSetAttribute(attn_tf32, cudaFuncAttributeMaxDynamicSharedMemorySize, attn_smem);
    attn_tf32<<<dim3(NB, NHEADS, BATCH), 128, attn_smem>>>(G);

    // O projection
    gemm_o<<<dim3(DMODEL / 128, MROWS / 128), 256, GEMM_SMEM>>>(ap_, bo, out);
}

// round 16
// speedup vs baseline: 1.2341x; 1.0137x over previous
#include <cuda_runtime.h>
#include <math.h>
#include <stdint.h>

#define BATCH   2
#define SEQ     2048
#define DMODEL  1024
#define NHEADS  16
#define HDIM    64
#define BLK     64
#define NB      (SEQ/BLK)         // 32 blocks per batch
#define MROWS   (BATCH*SEQ)       // 4096

#define QP      68                // qs/ks pitch (words)
#define VP      72                // vs pitch (words); cols 64..71 = ones column pad
#define APIT    20                // GEMM A smem pitch
#define BPIT    136               // GEMM B smem pitch

// Q scale folded with log2(e): softmax runs in exp2 domain.
#define QSCALE  0.18033688011112042f   // 0.125 * log2(e)

// Scratch (device globals: allocation-free, graph-capture safe).
__device__ __align__(16) uint32_t g_q[MROWS*DMODEL];
__device__ __align__(16) uint32_t g_k[MROWS*DMODEL];
__device__ __align__(16) uint32_t g_v[MROWS*DMODEL];
__device__ __align__(16) uint32_t g_attn[MROWS*DMODEL];
__device__ __align__(16) uint32_t g_xt[MROWS*DMODEL];      // x in tf32 bits
__device__ __align__(16) uint32_t g_wq[DMODEL*DMODEL];
__device__ __align__(16) uint32_t g_wk[DMODEL*DMODEL];
__device__ __align__(16) uint32_t g_wv[DMODEL*DMODEL];
__device__ __align__(16) uint32_t g_wo[DMODEL*DMODEL];

// ---------------------------------------------------------------------------
// helpers
// ---------------------------------------------------------------------------
__device__ __forceinline__ uint32_t f2tf32(float f) {
    uint32_t u;
    asm("cvt.rna.tf32.f32 %0, %1;" : "=r"(u) : "f"(f));
    return u;
}

__device__ __forceinline__ void mma_tf32(float* d, const uint32_t* a, const uint32_t* b) {
    asm volatile(
        "mma.sync.aligned.m16n8k8.row.col.f32.tf32.tf32.f32 "
        "{%0,%1,%2,%3}, {%4,%5,%6,%7}, {%8,%9}, {%0,%1,%2,%3};"
        : "+f"(d[0]), "+f"(d[1]), "+f"(d[2]), "+f"(d[3])
        : "r"(a[0]), "r"(a[1]), "r"(a[2]), "r"(a[3]),
          "r"(b[0]), "r"(b[1]));
}

__device__ __forceinline__ void cp16(uint32_t smem_addr, const void* gptr) {
    asm volatile("cp.async.cg.shared.global [%0], [%1], 16;\n"
                 :: "r"(smem_addr), "l"(gptr));
}
__device__ __forceinline__ void cp_commit() {
    asm volatile("cp.async.commit_group;\n" ::: "memory");
}
__device__ __forceinline__ void cp_wait_all() {
    asm volatile("cp.async.wait_group 0;\n" ::: "memory");
}
__device__ __forceinline__ void cp_wait_1() {
    asm volatile("cp.async.wait_group 1;\n" ::: "memory");
}

// ---------------------------------------------------------------------------
// fp32 -> tf32-bits conversion (x), and fused 4-weight variant
// ---------------------------------------------------------------------------
__global__ void conv_tf32(const float4* __restrict__ in, uint4* __restrict__ out, int n4)
{
    int i = blockIdx.x * blockDim.x + threadIdx.x;
    if (i < n4) {
        float4 v = in[i];
        out[i] = make_uint4(f2tf32(v.x), f2tf32(v.y), f2tf32(v.z), f2tf32(v.w));
    }
}

__global__ void conv_w4(const float4* w0, const float4* w1,
                        const float4* w2, const float4* w3, int n4)
{
    const float4* in;
    uint4* out;
    switch (blockIdx.y) {
        case 0:  in = w0; out = (uint4*)g_wq; break;
        case 1:  in = w1; out = (uint4*)g_wk; break;
        case 2:  in = w2; out = (uint4*)g_wv; break;
        default: in = w3; out = (uint4*)g_wo; break;
    }
    int i = blockIdx.x * blockDim.x + threadIdx.x;
    if (i < n4) {
        float4 v = in[i];
        out[i] = make_uint4(f2tf32(v.x), f2tf32(v.y), f2tf32(v.z), f2tf32(v.w));
    }
}

// ---------------------------------------------------------------------------
// GEMM core loop (3-stage cp.async pipeline), K = N = DMODEL.
// ---------------------------------------------------------------------------
#define GEMM_SMEM ((3*128*APIT + 3*16*BPIT) * 4)   // 56832 B

__device__ __forceinline__ void gemm_core(
    const uint32_t* __restrict__ A, const uint32_t* __restrict__ W,
    uint32_t* As, uint32_t* Bs, int bm, int bn,
    int tid, int m0, int n0, int gi, int tg, float acc[4][4][4])
{
    const int a_r = tid >> 2;
    const int a_o = (tid & 3) * 4;
    const int b_r = tid >> 5;
    const int b_o = (tid & 31) * 4;
    const int N = DMODEL, K = DMODEL;

    const uint32_t as_sa = (uint32_t)__cvta_generic_to_shared(As);
    const uint32_t bs_sa = (uint32_t)__cvta_generic_to_shared(Bs);

    auto issue = [&](int kt, int s) {
        const int ko = kt * 16;
        const uint32_t ab = as_sa + (uint32_t)(s * 128 * APIT * 4);
        const uint32_t bb = bs_sa + (uint32_t)(s * 16 * BPIT * 4);
        cp16(ab + (uint32_t)((a_r * APIT + a_o) * 4),
             A + (size_t)(bm + a_r) * K + ko + a_o);
        cp16(ab + (uint32_t)(((a_r + 64) * APIT + a_o) * 4),
             A + (size_t)(bm + a_r + 64) * K + ko + a_o);
        cp16(bb + (uint32_t)((b_r * BPIT + b_o) * 4),
             W + (size_t)(ko + b_r) * N + bn + b_o);
        cp16(bb + (uint32_t)(((b_r + 8) * BPIT + b_o) * 4),
             W + (size_t)(ko + b_r + 8) * N + bn + b_o);
        cp_commit();
    };

    const int nkt = K / 16;
    issue(0, 0);
    issue(1, 1);

    for (int kt = 0; kt < nkt; kt++) {
        const int s = kt % 3;
        cp_wait_1();
        __syncthreads();
        if (kt + 2 < nkt) issue(kt + 2, (kt + 2) % 3);

        const uint32_t* Ab = As + s * 128 * APIT;
        const uint32_t* Bb = Bs + s * 16 * BPIT;
#pragma unroll
        for (int ks = 0; ks < 2; ks++) {
            uint32_t af[4][4], bf[4][2];
#pragma unroll
            for (int mf = 0; mf < 4; mf++) {
                const uint32_t* p = &Ab[(m0 + 16*mf + gi) * APIT + 8*ks + tg];
                af[mf][0] = p[0];
                af[mf][1] = p[8 * APIT];
                af[mf][2] = p[4];
                af[mf][3] = p[8 * APIT + 4];
            }
#pragma unroll
            for (int nf = 0; nf < 4; nf++) {
                bf[nf][0] = Bb[(8*ks + tg) * BPIT + n0 + 8*nf + gi];
                bf[nf][1] = Bb[(8*ks + tg + 4) * BPIT + n0 + 8*nf + gi];
            }
#pragma unroll
            for (int mf = 0; mf < 4; mf++)
#pragma unroll
                for (int nf = 0; nf < 4; nf++)
                    mma_tf32(acc[mf][nf], af[mf], bf[nf]);
        }
    }
}

// ---------------------------------------------------------------------------
// Fused Q/K/V projection (grid.z = 0/1/2).
// z=0: Q (tf32 bits of QSCALE*(acc+bias)); z=1: K; z=2: V (tf32 bits).
// ---------------------------------------------------------------------------
__global__ __launch_bounds__(256, 2)
void gemm_qkv(const uint32_t* __restrict__ A,
              const float* __restrict__ bq, const float* __restrict__ bk,
              const float* __restrict__ bv)
{
    const int z  = blockIdx.z;
    const int bm = blockIdx.y * 128;
    const int bn = blockIdx.x * 128;

    const uint32_t* W;
    const float* bias;
    uint32_t* C;
    if      (z == 0) { W = g_wq; bias = bq; C = g_q; }
    else if (z == 1) { W = g_wk; bias = bk; C = g_k; }
    else             { W = g_wv; bias = bv; C = g_v; }

    extern __shared__ uint32_t gsm[];
    uint32_t* As = gsm;
    uint32_t* Bs = gsm + 3 * 128 * APIT;

    const int tid  = threadIdx.x;
    const int lane = tid & 31;
    const int wid  = tid >> 5;
    const int gi   = lane >> 2;
    const int tg   = lane & 3;
    const int m0   = (wid >> 2) * 64;
    const int n0   = (wid & 3) * 32;

    float acc[4][4][4];
#pragma unroll
    for (int i = 0; i < 4; i++)
#pragma unroll
        for (int j = 0; j < 4; j++)
#pragma unroll
            for (int r = 0; r < 4; r++) acc[i][j][r] = 0.f;

    gemm_core(A, W, As, Bs, bm, bn, tid, m0, n0, gi, tg, acc);

#pragma unroll
    for (int mf = 0; mf < 4; mf++) {
        const int r0 = bm + m0 + 16*mf + gi;
        const int r1 = r0 + 8;
#pragma unroll
        for (int nf = 0; nf < 4; nf++) {
            const int c = bn + n0 + 8*nf + 2*tg;
            float2 bi = *(const float2*)&bias[c];
            float v00 = acc[mf][nf][0] + bi.x, v01 = acc[mf][nf][1] + bi.y;
            float v10 = acc[mf][nf][2] + bi.x, v11 = acc[mf][nf][3] + bi.y;
            if (z == 0) { v00 *= QSCALE; v01 *= QSCALE; v10 *= QSCALE; v11 *= QSCALE; }
            *(uint2*)&C[(size_t)r0 * DMODEL + c] = make_uint2(f2tf32(v00), f2tf32(v01));
            *(uint2*)&C[(size_t)r1 * DMODEL + c] = make_uint2(f2tf32(v10), f2tf32(v11));
        }
    }
}

// ---------------------------------------------------------------------------
// O projection: fp32 out.
// ---------------------------------------------------------------------------
__global__ __launch_bounds__(256, 2)
void gemm_o(const uint32_t* __restrict__ A, const float* __restrict__ bias,
            float* __restrict__ C)
{
    const int bm = blockIdx.y * 128;
    const int bn = blockIdx.x * 128;

    extern __shared__ uint32_t gsm[];
    uint32_t* As = gsm;
    uint32_t* Bs = gsm + 3 * 128 * APIT;

    const int tid  = threadIdx.x;
    const int lane = tid & 31;
    const int wid  = tid >> 5;
    const int gi   = lane >> 2;
    const int tg   = lane & 3;
    const int m0   = (wid >> 2) * 64;
    const int n0   = (wid & 3) * 32;

    float acc[4][4][4];
#pragma unroll
    for (int i = 0; i < 4; i++)
#pragma unroll
        for (int j = 0; j < 4; j++)
#pragma unroll
            for (int r = 0; r < 4; r++) acc[i][j][r] = 0.f;

    gemm_core(A, g_wo, As, Bs, bm, bn, tid, m0, n0, gi, tg, acc);

#pragma unroll
    for (int mf = 0; mf < 4; mf++) {
        const int r0 = bm + m0 + 16*mf + gi;
        const int r1 = r0 + 8;
#pragma unroll
        for (int nf = 0; nf < 4; nf++) {
            const int c = bn + n0 + 8*nf + 2*tg;
            float2 bi = *(const float2*)&bias[c];
            *(float2*)&C[(size_t)r0 * DMODEL + c] =
                make_float2(acc[mf][nf][0] + bi.x, acc[mf][nf][1] + bi.y);
            *(float2*)&C[(size_t)r1 * DMODEL + c] =
                make_float2(acc[mf][nf][2] + bi.x, acc[mf][nf][3] + bi.y);
        }
    }
}

// ---------------------------------------------------------------------------
// TF32 flash attention v7: v6 math (exp2 softmax, l via ones-column mma)
// with smem cut to 71,680 B for 3 CTAs/SM:
//   K single-buffered  (K(kb+1) issued after QK(kb) + syncthreads)
//   V double-buffered  (V(kb+1) issued at tile start)
// smem: qs/P [64][QP], ks [64][QP], vs 2x[64][VP].
// ---------------------------------------------------------------------------
__global__ __launch_bounds__(128, 3)
void attn_tf32(const float* __restrict__ G)
{
    extern __shared__ uint32_t sm[];
    uint32_t* qs = sm;                               // Q staging then P
    uint32_t* ks = sm + 64 * QP;                     // 1 x [64][QP]
    uint32_t* vs = sm + 2 * 64 * QP;                 // 2 x [64][VP]
    __shared__ float kbuf[64];

    const int qb = blockIdx.x, h = blockIdx.y, b = blockIdx.z;
    const int tid  = threadIdx.x;
    const int lane = tid & 31;
    const int w    = tid >> 5;
    const int gi   = lane >> 2;
    const int tg   = lane & 3;

    // ---- keep check ----
    if (tid < 64) kbuf[tid] = fabsf(G[b * SEQ + qb * BLK + tid]);
    __syncthreads();
    float bmax = 0.f;
#pragma unroll
    for (int i = 0; i < 64; i++) bmax = fmaxf(bmax, kbuf[i]);

    if (bmax < 0.99f) {
        const uint4 z = make_uint4(0u, 0u, 0u, 0u);
#pragma unroll
        for (int i = 0; i < 8; i++) {
            int c = tid + i * 128;
            int r = c >> 4;
            int o = (c & 15) * 4;
            *(uint4*)&g_attn[(size_t)(b * SEQ + qb * BLK + r) * DMODEL + h * HDIM + o] = z;
        }
        return;
    }

    // ---- one-time ones-column init for BOTH V buffers (cols 64..71) ----
    {
        uint32_t* p = &vs[tid * VP + 64];        // rows 0..127 span both buffers
        *(uint4*)p       = make_uint4(0x3F800000u, 0u, 0u, 0u);  // 1.0, 0, 0, 0
        *(uint4*)(p + 4) = make_uint4(0u, 0u, 0u, 0u);
    }

    const uint32_t qs_sa = (uint32_t)__cvta_generic_to_shared(qs);
    const uint32_t ks_sa = (uint32_t)__cvta_generic_to_shared(ks);
    const uint32_t vs_sa = (uint32_t)__cvta_generic_to_shared(vs);

    // ---- prologue: Q + K(0) + V(0) via cp.async (one group) ----
#pragma unroll
    for (int i = 0; i < 8; i++) {
        int c = tid + i * 128;
        int r = c >> 4;
        int o = (c & 15) * 4;
        size_t qsrc = (size_t)(b * SEQ + qb * BLK + r) * DMODEL + h * HDIM + o;
        size_t ksrc = (size_t)(b * SEQ + r) * DMODEL + h * HDIM + o;
        cp16(qs_sa + (uint32_t)((r * QP + o) * 4), g_q + qsrc);
        cp16(ks_sa + (uint32_t)((r * QP + o) * 4), g_k + ksrc);
        cp16(vs_sa + (uint32_t)((r * VP + o) * 4), g_v + ksrc);
    }
    cp_commit();

    uint32_t qa[8][4];
    float o_[8][4];
    float lacc[4] = {0.f, 0.f, 0.f, 0.f};            // l via ones-column of V
#pragma unroll
    for (int nf = 0; nf < 8; nf++)
#pragma unroll
        for (int r = 0; r < 4; r++) o_[nf][r] = 0.f;
    float m0r = -1e30f, m1r = -1e30f;

    for (int kb = 0; kb < NB; kb++) {
        const int buf = kb & 1;
        // K(kb), V(kb) resident after this (V(kb) issued a full tile ago,
        // K(kb) issued after QK(kb-1), hidden by softmax+PV(kb-1)).
        cp_wait_all();
        __syncthreads();

        if (kb == 0) {
#pragma unroll
            for (int k8 = 0; k8 < 8; k8++) {
                const uint32_t* q = &qs[(16*w + gi) * QP + 8*k8 + tg];
                qa[k8][0] = q[0];
                qa[k8][1] = q[8 * QP];
                qa[k8][2] = q[4];
                qa[k8][3] = q[8 * QP + 4];
            }
        }

        // issue V(kb+1) into the other V buffer (hidden by whole tile kb)
        if (kb + 1 < NB) {
            const uint32_t vd = vs_sa + (uint32_t)((buf ^ 1) * 64 * VP * 4);
#pragma unroll
            for (int i = 0; i < 8; i++) {
                int c = tid + i * 128;
                int r = c >> 4;
                int o = (c & 15) * 4;
                size_t src = (size_t)(b * SEQ + (kb + 1) * BLK + r) * DMODEL + h * HDIM + o;
                cp16(vd + (uint32_t)((r * VP + o) * 4), g_v + src);
            }
            cp_commit();
        }

        // ---- S = Q K^T (reads single K buffer) ----
        float sc[8][4];
#pragma unroll
        for (int nf = 0; nf < 8; nf++)
            sc[nf][0] = sc[nf][1] = sc[nf][2] = sc[nf][3] = 0.f;
#pragma unroll
        for (int k8 = 0; k8 < 8; k8++)
#pragma unroll
            for (int nf = 0; nf < 8; nf++) {
                uint32_t bfr[2];
                bfr[0] = ks[(8*nf + gi) * QP + 8*k8 + tg];
                bfr[1] = ks[(8*nf + gi) * QP + 8*k8 + 4 + tg];
                mma_tf32(sc[nf], qa[k8], bfr);
            }

        // all warps done reading K(kb) -> safe to overwrite the K buffer
        __syncthreads();
        if (kb + 1 < NB) {
#pragma unroll
            for (int i = 0; i < 8; i++) {
                int c = tid + i * 128;
                int r = c >> 4;
                int o = (c & 15) * 4;
                size_t src = (size_t)(b * SEQ + (kb + 1) * BLK + r) * DMODEL + h * HDIM + o;
                cp16(ks_sa + (uint32_t)((r * QP + o) * 4), g_k + src);
            }
            cp_commit();
        }

        // ---- online softmax: max-reduce only (sum comes from PV) ----
        float mb0 = -1e30f, mb1 = -1e30f;
#pragma unroll
        for (int nf = 0; nf < 8; nf++) {
            mb0 = fmaxf(mb0, fmaxf(sc[nf][0], sc[nf][1]));
            mb1 = fmaxf(mb1, fmaxf(sc[nf][2], sc[nf][3]));
        }
        mb0 = fmaxf(mb0, __shfl_xor_sync(0xffffffffu, mb0, 1));
        mb0 = fmaxf(mb0, __shfl_xor_sync(0xffffffffu, mb0, 2));
        mb1 = fmaxf(mb1, __shfl_xor_sync(0xffffffffu, mb1, 1));
        mb1 = fmaxf(mb1, __shfl_xor_sync(0xffffffffu, mb1, 2));
        const float mn0 = fmaxf(m0r, mb0);
        const float mn1 = fmaxf(m1r, mb1);
        const float al0 = exp2f(m0r - mn0);
        const float al1 = exp2f(m1r - mn1);
        m0r = mn0; m1r = mn1;

        const int pr0 = (16*w + gi) * QP;
        const int pr1 = pr0 + 8 * QP;
#pragma unroll
        for (int nf = 0; nf < 8; nf++) {
            float p0 = exp2f(sc[nf][0] - mn0);
            float p1 = exp2f(sc[nf][1] - mn0);
            float p2 = exp2f(sc[nf][2] - mn1);
            float p3 = exp2f(sc[nf][3] - mn1);
            const int c = 8*nf + 2*tg;
            *(uint2*)&qs[pr0 + c] = make_uint2(f2tf32(p0), f2tf32(p1));
            *(uint2*)&qs[pr1 + c] = make_uint2(f2tf32(p2), f2tf32(p3));
        }
#pragma unroll
        for (int nf = 0; nf < 8; nf++) {
            o_[nf][0] *= al0; o_[nf][1] *= al0;
            o_[nf][2] *= al1; o_[nf][3] *= al1;
        }
        lacc[0] *= al0; lacc[1] *= al0;
        lacc[2] *= al1; lacc[3] *= al1;
        __syncwarp();   // P rows warp-private: store->read ordering

        // ---- O += P V ; l += P @ ones (V col 64) ----
        const uint32_t* vsb = vs + buf * 64 * VP;
#pragma unroll
        for (int k8 = 0; k8 < 8; k8++) {
            uint32_t pa[4];
            const uint32_t* pp = &qs[(16*w + gi) * QP + 8*k8 + tg];
            pa[0] = pp[0];
            pa[1] = pp[8 * QP];
            pa[2] = pp[4];
            pa[3] = pp[8 * QP + 4];
#pragma unroll
            for (int nf = 0; nf < 8; nf++) {
                uint32_t bfr[2];
                bfr[0] = vsb[(8*k8 + tg) * VP + 8*nf + gi];
                bfr[1] = vsb[(8*k8 + tg + 4) * VP + 8*nf + gi];
                mma_tf32(o_[nf], pa, bfr);
            }
            {   // ones-column group (cols 64..71; col 64 = 1.0, rest 0)
                uint32_t bfr[2];
                bfr[0] = vsb[(8*k8 + tg) * VP + 64 + gi];
                bfr[1] = vsb[(8*k8 + tg + 4) * VP + 64 + gi];
                mma_tf32(lacc, pa, bfr);
            }
        }
    }

    // ---- epilogue: l lives in tg=0 lanes (col 64 = local col 0) ----
    const float l0 = __shfl_sync(0xffffffffu, lacc[0], lane & ~3);
    const float l1 = __shfl_sync(0xffffffffu, lacc[2], lane & ~3);
    const float inv0 = 1.0f / l0;
    const float inv1 = 1.0f / l1;
    const size_t rb0 = (size_t)(b * SEQ + qb * BLK + 16*w + gi) * DMODEL + h * HDIM;
    const size_t rb1 = rb0 + (size_t)8 * DMODEL;
#pragma unroll
    for (int nf = 0; nf < 8; nf++) {
        const int c = 8*nf + 2*tg;
        *(uint2*)&g_attn[rb0 + c] = make_uint2(f2tf32(o_[nf][0] * inv0),
                                               f2tf32(o_[nf][1] * inv0));
        *(uint2*)&g_attn[rb1 + c] = make_uint2(f2tf32(o_[nf][2] * inv1),
                                               f2tf32(o_[nf][3] * inv1));
    }
}

// ---------------------------------------------------------------------------
extern "C" void kernel_launch(void* const* d_in, const int* in_sizes, int n_in,
                              void* d_out, int out_size)
{
    const float* x  = (const float*)d_in[0];
    const float* G  = (const float*)d_in[1];
    const float* Wq = (const float*)d_in[2];
    const float* bq = (const float*)d_in[3];
    const float* Wk = (const float*)d_in[4];
    const float* bk = (const float*)d_in[5];
    const float* Wv = (const float*)d_in[6];
    const float* bv = (const float*)d_in[7];
    const float* Wo = (const float*)d_in[8];
    const float* bo = (const float*)d_in[9];
    float* out = (float*)d_out;

    uint32_t *ap_, *xt_;
    cudaGetSymbolAddress((void**)&ap_, g_attn);
    cudaGetSymbolAddress((void**)&xt_, g_xt);

    // tf32 pre-conversion (x + fused 4 weights)
    const int xn4 = MROWS * DMODEL / 4;
    const int wn4 = DMODEL * DMODEL / 4;
    conv_tf32<<<(xn4 + 255) / 256, 256>>>((const float4*)x, (uint4*)xt_, xn4);
    conv_w4<<<dim3((wn4 + 255) / 256, 4), 256>>>((const float4*)Wq, (const float4*)Wk,
                                                 (const float4*)Wv, (const float4*)Wo, wn4);

    cudaFuncSetAttribute(gemm_qkv, cudaFuncAttributeMaxDynamicSharedMemorySize, GEMM_SMEM);
    cudaFuncSetAttribute(gemm_o,   cudaFuncAttributeMaxDynamicSharedMemorySize, GEMM_SMEM);

    // fused Q/K/V projections
    gemm_qkv<<<dim3(DMODEL / 128, MROWS / 128, 3), 256, GEMM_SMEM>>>(xt_, bq, bk, bv);

    // attention: qs + 1x K + 2x V = 71,680 B -> 3 CTAs/SM
    const int attn_smem = (64 * QP + 64 * QP + 2 * 64 * VP) * (int)sizeof(uint32_t);
    cudaFuncSetAttribute(attn_tf32, cudaFuncAttributeMaxDynamicSharedMemorySize, attn_smem);
    attn_tf32<<<dim3(NB, NHEADS, BATCH), 128, attn_smem>>>(G);

    // O projection
    gemm_o<<<dim3(DMODEL / 128, MROWS / 128), 256, GEMM_SMEM>>>(ap_, bo, out);
}